// round 2
// baseline (speedup 1.0000x reference)
#include <cuda_runtime.h>

// Problem constants
#define S_LEN 2048
#define BATCH 2
#define NHEAD 16
#define HD    64
#define DM    1024
#define MROWS (BATCH * S_LEN)   // 4096

// Scratch (device globals: no allocations allowed)
__device__ float g_kv [MROWS * 2 * DM];   // 4096 x 2048  (k,v projections)
__device__ float g_q  [MROWS * DM];       // 4096 x 1024
__device__ float g_att[MROWS * DM];       // 4096 x 1024  (attention output)

// ---------------------------------------------------------------------------
// Tiled SGEMM with bias: C[M,N] = A[M,K] @ W[K,N] + bias[N]
// 128x128 tile, BK=8, 256 threads, 8x8 register micro-tile per thread.
// M,N multiples of 128; K multiple of 8. All pointers 16B aligned rows.
// ---------------------------------------------------------------------------
#define BM 128
#define BN 128
#define BK 8

__global__ __launch_bounds__(256) void sgemm_bias(
    const float* __restrict__ A, const float* __restrict__ W,
    const float* __restrict__ bias, float* __restrict__ C,
    int M, int N, int K)
{
    __shared__ float As[BK][BM];
    __shared__ float Bs[BK][BN];

    const int t  = threadIdx.x;
    const int m0 = blockIdx.y * BM;
    const int n0 = blockIdx.x * BN;
    const int tx = t & 15;
    const int ty = t >> 4;

    // A tile loader: 128 rows x 8 cols, one float4 per thread
    const int arow = t >> 1;          // 0..127
    const int acol = (t & 1) * 4;     // 0 or 4
    // B tile loader: 8 rows x 128 cols, one float4 per thread
    const int brow = t >> 5;          // 0..7
    const int bcol = (t & 31) * 4;    // 0..124

    const float* Aptr = A + (size_t)(m0 + arow) * K + acol;
    const float* Bptr = W + (size_t)brow * N + n0 + bcol;

    float acc[8][8];
    #pragma unroll
    for (int i = 0; i < 8; i++)
        #pragma unroll
        for (int j = 0; j < 8; j++) acc[i][j] = 0.0f;

    for (int k0 = 0; k0 < K; k0 += BK) {
        float4 av = *(const float4*)(Aptr + k0);
        float4 bv = *(const float4*)(Bptr + (size_t)k0 * N);
        As[acol + 0][arow] = av.x;
        As[acol + 1][arow] = av.y;
        As[acol + 2][arow] = av.z;
        As[acol + 3][arow] = av.w;
        *(float4*)&Bs[brow][bcol] = bv;
        __syncthreads();

        #pragma unroll
        for (int kk = 0; kk < BK; kk++) {
            float4 a0 = *(const float4*)&As[kk][ty * 8 + 0];
            float4 a1 = *(const float4*)&As[kk][ty * 8 + 4];
            float4 b0 = *(const float4*)&Bs[kk][tx * 8 + 0];
            float4 b1 = *(const float4*)&Bs[kk][tx * 8 + 4];
            float a[8] = {a0.x, a0.y, a0.z, a0.w, a1.x, a1.y, a1.z, a1.w};
            float b[8] = {b0.x, b0.y, b0.z, b0.w, b1.x, b1.y, b1.z, b1.w};
            #pragma unroll
            for (int i = 0; i < 8; i++)
                #pragma unroll
                for (int j = 0; j < 8; j++)
                    acc[i][j] += a[i] * b[j];
        }
        __syncthreads();
    }

    // epilogue with bias
    #pragma unroll
    for (int i = 0; i < 8; i++) {
        const int m = m0 + ty * 8 + i;
        float* crow = C + (size_t)m * N + n0 + tx * 8;
        #pragma unroll
        for (int j = 0; j < 8; j++)
            crow[j] = acc[i][j] + bias[n0 + tx * 8 + j];
    }
}

// ---------------------------------------------------------------------------
// Flash attention (fp32): per CTA = one (b,h) and a BQ=64 query block.
// Streams K/V blocks of BKV=64, online softmax. 256 threads, 4x4 micro-tiles.
// ---------------------------------------------------------------------------
#define BQ   64
#define BKV  64
#define PADD 65   // smem row pad to break bank conflicts

#define FLASH_SMEM_FLOATS (3 * BQ * PADD + 3 * BQ)
#define FLASH_SMEM_BYTES  (FLASH_SMEM_FLOATS * 4)

__global__ __launch_bounds__(256) void flash_attn()
{
    extern __shared__ float sm[];
    float* Qs   = sm;                    // [BQ][PADD]  (scaled Q)
    float* KVs  = Qs  + BQ * PADD;       // [BKV][PADD] (K, then V)
    float* Ps   = KVs + BKV * PADD;      // [BQ][PADD]  (scores -> probs)
    float* m_sh = Ps  + BQ * PADD;       // [BQ]
    float* l_sh = m_sh + BQ;             // [BQ]
    float* a_sh = l_sh + BQ;             // [BQ]

    const int t  = threadIdx.x;
    const int bh = blockIdx.y;
    const int b  = bh >> 4;
    const int h  = bh & 15;
    const int q0 = blockIdx.x * BQ;
    const float scale = 0.125f;          // 1/sqrt(64)

    // Load Q tile (pre-scaled)
    for (int i = t; i < BQ * (HD / 4); i += 256) {
        int r = i >> 4;
        int d = (i & 15) * 4;
        float4 v = *(const float4*)&g_q[(size_t)(b * S_LEN + q0 + r) * DM + h * HD + d];
        float* dst = &Qs[r * PADD + d];
        dst[0] = v.x * scale; dst[1] = v.y * scale;
        dst[2] = v.z * scale; dst[3] = v.w * scale;
    }
    if (t < BQ) { m_sh[t] = -1e30f; l_sh[t] = 0.0f; }

    const int tx = t & 15;
    const int ty = t >> 4;
    const int r0 = ty * 4;
    const int c0 = tx * 4;

    float o[4][4];
    #pragma unroll
    for (int i = 0; i < 4; i++)
        #pragma unroll
        for (int j = 0; j < 4; j++) o[i][j] = 0.0f;

    const int row = t >> 2;   // softmax row team
    const int g   = t & 3;

    for (int kb = 0; kb < S_LEN / BKV; kb++) {
        __syncthreads();   // previous PV done reading KVs (also covers Q/m/l init)
        const int k0 = kb * BKV;

        // Load K block: KV[(b*S + k), h*128 + d]
        for (int i = t; i < BKV * (HD / 4); i += 256) {
            int r = i >> 4;
            int d = (i & 15) * 4;
            float4 v = *(const float4*)&g_kv[(size_t)(b * S_LEN + k0 + r) * (2 * DM) + h * 2 * HD + d];
            float* dst = &KVs[r * PADD + d];
            dst[0] = v.x; dst[1] = v.y; dst[2] = v.z; dst[3] = v.w;
        }
        __syncthreads();

        // S = Qs @ Ks^T  (4x4 micro-tile per thread)
        float s[4][4];
        #pragma unroll
        for (int i = 0; i < 4; i++)
            #pragma unroll
            for (int j = 0; j < 4; j++) s[i][j] = 0.0f;

        #pragma unroll 8
        for (int d = 0; d < HD; d++) {
            float a[4], bb[4];
            #pragma unroll
            for (int i = 0; i < 4; i++) a[i] = Qs[(r0 + i) * PADD + d];
            #pragma unroll
            for (int j = 0; j < 4; j++) bb[j] = KVs[(c0 + j) * PADD + d];
            #pragma unroll
            for (int i = 0; i < 4; i++)
                #pragma unroll
                for (int j = 0; j < 4; j++)
                    s[i][j] += a[i] * bb[j];
        }
        // write raw scores
        #pragma unroll
        for (int i = 0; i < 4; i++)
            #pragma unroll
            for (int j = 0; j < 4; j++)
                Ps[(r0 + i) * PADD + c0 + j] = s[i][j];
        __syncthreads();

        // Load V block into KVs (K reads are complete)
        for (int i = t; i < BKV * (HD / 4); i += 256) {
            int r = i >> 4;
            int d = (i & 15) * 4;
            float4 v = *(const float4*)&g_kv[(size_t)(b * S_LEN + k0 + r) * (2 * DM) + h * 2 * HD + HD + d];
            float* dst = &KVs[r * PADD + d];
            dst[0] = v.x; dst[1] = v.y; dst[2] = v.z; dst[3] = v.w;
        }

        // Online softmax: 4 threads per row, 16 cols each
        {
            float* prow = Ps + row * PADD + g * 16;
            float mx = -1e30f;
            #pragma unroll
            for (int j = 0; j < 16; j++) mx = fmaxf(mx, prow[j]);
            mx = fmaxf(mx, __shfl_xor_sync(0xffffffffu, mx, 1));
            mx = fmaxf(mx, __shfl_xor_sync(0xffffffffu, mx, 2));
            const float m_old = m_sh[row];
            const float m_new = fmaxf(m_old, mx);
            float lsum = 0.0f;
            #pragma unroll
            for (int j = 0; j < 16; j++) {
                float e = __expf(prow[j] - m_new);
                prow[j] = e;
                lsum += e;
            }
            lsum += __shfl_xor_sync(0xffffffffu, lsum, 1);
            lsum += __shfl_xor_sync(0xffffffffu, lsum, 2);
            if (g == 0) {
                float al = __expf(m_old - m_new);
                a_sh[row] = al;
                m_sh[row] = m_new;
                l_sh[row] = l_sh[row] * al + lsum;
            }
        }
        __syncthreads();

        // Rescale O accumulators, then O += P @ V
        #pragma unroll
        for (int i = 0; i < 4; i++) {
            float al = a_sh[r0 + i];
            #pragma unroll
            for (int j = 0; j < 4; j++) o[i][j] *= al;
        }
        #pragma unroll 8
        for (int kk = 0; kk < BKV; kk++) {
            float p[4], v[4];
            #pragma unroll
            for (int i = 0; i < 4; i++) p[i] = Ps[(r0 + i) * PADD + kk];
            #pragma unroll
            for (int j = 0; j < 4; j++) v[j] = KVs[kk * PADD + c0 + j];
            #pragma unroll
            for (int i = 0; i < 4; i++)
                #pragma unroll
                for (int j = 0; j < 4; j++)
                    o[i][j] += p[i] * v[j];
        }
    }

    // Normalize and write to g_att[b, q, h*64 + c]
    #pragma unroll
    for (int i = 0; i < 4; i++) {
        float inv = 1.0f / l_sh[r0 + i];
        float* dst = &g_att[(size_t)(b * S_LEN + q0 + r0 + i) * DM + h * HD + c0];
        #pragma unroll
        for (int j = 0; j < 4; j++)
            dst[j] = o[i][j] * inv;
    }
}

// ---------------------------------------------------------------------------
// Host launcher (graph-capturable: kernel launches only)
// ---------------------------------------------------------------------------
extern "C" void kernel_launch(void* const* d_in, const int* in_sizes, int n_in,
                              void* d_out, int out_size)
{
    const float* x   = (const float*)d_in[0];
    const float* y   = (const float*)d_in[1];
    const float* Wkv = (const float*)d_in[2];
    const float* bkv = (const float*)d_in[3];
    const float* Wq  = (const float*)d_in[4];
    const float* bq  = (const float*)d_in[5];
    const float* Wo  = (const float*)d_in[6];
    const float* bo  = (const float*)d_in[7];
    float* out = (float*)d_out;

    float *kv, *q, *att;
    cudaGetSymbolAddress((void**)&kv,  g_kv);
    cudaGetSymbolAddress((void**)&q,   g_q);
    cudaGetSymbolAddress((void**)&att, g_att);

    cudaFuncSetAttribute(flash_attn,
                         cudaFuncAttributeMaxDynamicSharedMemorySize,
                         FLASH_SMEM_BYTES);

    dim3 blk(256);

    // kv = x @ Wkv + bkv    [4096, 2048]
    sgemm_bias<<<dim3(2 * DM / BN, MROWS / BM), blk>>>(x, Wkv, bkv, kv, MROWS, 2 * DM, DM);
    // q  = y @ Wq  + bq     [4096, 1024]
    sgemm_bias<<<dim3(DM / BN, MROWS / BM), blk>>>(y, Wq, bq, q, MROWS, DM, DM);
    // attention -> g_att    [4096, 1024]
    flash_attn<<<dim3(S_LEN / BQ, BATCH * NHEAD), blk, FLASH_SMEM_BYTES>>>();
    // out = att @ Wo + bo   [4096, 1024]
    sgemm_bias<<<dim3(DM / BN, MROWS / BM), blk>>>(att, Wo, bo, out, MROWS, DM, DM);
}

// round 3
// speedup vs baseline: 1.0945x; 1.0945x over previous
#include <cuda_runtime.h>

// Problem constants
#define S_LEN 2048
#define BATCH 2
#define NHEAD 16
#define HD    64
#define DM    1024
#define MROWS (BATCH * S_LEN)   // 4096

// Scratch (device globals: no allocations allowed)
__device__ float g_kv [MROWS * 2 * DM];   // 4096 x 2048  (k,v projections)
__device__ float g_q  [MROWS * DM];       // 4096 x 1024
__device__ float g_att[MROWS * DM];       // 4096 x 1024  (attention output)

// ---------------------------------------------------------------------------
// Tiled SGEMM with bias: C[M,N] = A[M,K] @ W[K,N] + bias[N]
// 128x128 tile, BK=8, 256 threads, 8x8 register micro-tile per thread.
// (unchanged from round 2 — measured 74.7 TF/s)
// ---------------------------------------------------------------------------
#define BM 128
#define BN 128
#define BK 8

__global__ __launch_bounds__(256) void sgemm_bias(
    const float* __restrict__ A, const float* __restrict__ W,
    const float* __restrict__ bias, float* __restrict__ C,
    int M, int N, int K)
{
    __shared__ float As[BK][BM];
    __shared__ float Bs[BK][BN];

    const int t  = threadIdx.x;
    const int m0 = blockIdx.y * BM;
    const int n0 = blockIdx.x * BN;
    const int tx = t & 15;
    const int ty = t >> 4;

    const int arow = t >> 1;
    const int acol = (t & 1) * 4;
    const int brow = t >> 5;
    const int bcol = (t & 31) * 4;

    const float* Aptr = A + (size_t)(m0 + arow) * K + acol;
    const float* Bptr = W + (size_t)brow * N + n0 + bcol;

    float acc[8][8];
    #pragma unroll
    for (int i = 0; i < 8; i++)
        #pragma unroll
        for (int j = 0; j < 8; j++) acc[i][j] = 0.0f;

    for (int k0 = 0; k0 < K; k0 += BK) {
        float4 av = *(const float4*)(Aptr + k0);
        float4 bv = *(const float4*)(Bptr + (size_t)k0 * N);
        As[acol + 0][arow] = av.x;
        As[acol + 1][arow] = av.y;
        As[acol + 2][arow] = av.z;
        As[acol + 3][arow] = av.w;
        *(float4*)&Bs[brow][bcol] = bv;
        __syncthreads();

        #pragma unroll
        for (int kk = 0; kk < BK; kk++) {
            float4 a0 = *(const float4*)&As[kk][ty * 8 + 0];
            float4 a1 = *(const float4*)&As[kk][ty * 8 + 4];
            float4 b0 = *(const float4*)&Bs[kk][tx * 8 + 0];
            float4 b1 = *(const float4*)&Bs[kk][tx * 8 + 4];
            float a[8] = {a0.x, a0.y, a0.z, a0.w, a1.x, a1.y, a1.z, a1.w};
            float b[8] = {b0.x, b0.y, b0.z, b0.w, b1.x, b1.y, b1.z, b1.w};
            #pragma unroll
            for (int i = 0; i < 8; i++)
                #pragma unroll
                for (int j = 0; j < 8; j++)
                    acc[i][j] += a[i] * b[j];
        }
        __syncthreads();
    }

    #pragma unroll
    for (int i = 0; i < 8; i++) {
        const int m = m0 + ty * 8 + i;
        float* crow = C + (size_t)m * N + n0 + tx * 8;
        #pragma unroll
        for (int j = 0; j < 8; j++)
            crow[j] = acc[i][j] + bias[n0 + tx * 8 + j];
    }
}

// ---------------------------------------------------------------------------
// Flash attention v2 (fp32), SGEMM-style register blocking.
// CTA = one (b,h) x 128-query block. Streams KV in blocks of 128.
//  - S = Q@K^T with 8x8 micro-tiles (16x16 thread grid), Q/K transposed in smem
//  - online softmax fully in registers (half-warp shfl reductions)
//  - P@V with 8x4 micro-tiles, P loads broadcast, V loads conflict-free
// ---------------------------------------------------------------------------
#define BQ2  128
#define BKV2 128
#define QK_STR 132     // stride for transposed Q/K tiles [d][r]
#define V_STR  68      // stride for V tile [k][c]
#define P_STR  132     // stride for P tile [r][k]

#define FLASH2_SMEM_FLOATS (2 * 64 * QK_STR + BKV2 * V_STR + BQ2 * P_STR)
#define FLASH2_SMEM_BYTES  (FLASH2_SMEM_FLOATS * 4)

__global__ __launch_bounds__(256) void flash_attn2()
{
    extern __shared__ float sm[];
    float* Qs = sm;                       // [64][QK_STR]  Q^T (scaled)
    float* Ks = Qs + 64 * QK_STR;         // [64][QK_STR]  K^T
    float* Vs = Ks + 64 * QK_STR;         // [BKV2][V_STR] V natural
    float* Ps = Vs + BKV2 * V_STR;        // [BQ2][P_STR]  probabilities

    const int t   = threadIdx.x;
    const int bh  = blockIdx.y;
    const int b   = bh >> 4;
    const int h   = bh & 15;
    const int q0  = blockIdx.x * BQ2;
    const int tx  = t & 15;
    const int ty  = t >> 4;
    const int r0  = ty * 8;     // S rows / O rows for this thread
    const int c0  = tx * 8;     // S cols
    const int c0v = tx * 4;     // O cols
    const float scale = 0.125f; // 1/sqrt(64)

    // ---- Load Q tile transposed + pre-scaled: Qs[d][r] ----
    {
        const float* qbase = g_q + (size_t)(b * S_LEN + q0) * DM + h * HD;
        #pragma unroll
        for (int it = 0; it < 8; it++) {
            int idx = t + it * 256;          // 0..2047
            int r = idx >> 4;                // 0..127
            int d = (idx & 15) * 4;          // 0..60
            float4 v = *(const float4*)(qbase + (size_t)r * DM + d);
            Qs[(d + 0) * QK_STR + r] = v.x * scale;
            Qs[(d + 1) * QK_STR + r] = v.y * scale;
            Qs[(d + 2) * QK_STR + r] = v.z * scale;
            Qs[(d + 3) * QK_STR + r] = v.w * scale;
        }
    }

    float m_r[8], l_r[8];
    float o[8][4];
    #pragma unroll
    for (int i = 0; i < 8; i++) {
        m_r[i] = -1e30f;
        l_r[i] = 0.0f;
        #pragma unroll
        for (int c = 0; c < 4; c++) o[i][c] = 0.0f;
    }

    for (int kb = 0; kb < S_LEN / BKV2; kb++) {
        __syncthreads();   // previous block's smem reads complete (also covers Q load on kb=0)

        const float* kvbase = g_kv + (size_t)(b * S_LEN + kb * BKV2) * (2 * DM) + h * 2 * HD;

        // K tile transposed: Ks[d][r]
        #pragma unroll
        for (int it = 0; it < 8; it++) {
            int idx = t + it * 256;
            int r = idx >> 4;
            int d = (idx & 15) * 4;
            float4 v = *(const float4*)(kvbase + (size_t)r * (2 * DM) + d);
            Ks[(d + 0) * QK_STR + r] = v.x;
            Ks[(d + 1) * QK_STR + r] = v.y;
            Ks[(d + 2) * QK_STR + r] = v.z;
            Ks[(d + 3) * QK_STR + r] = v.w;
        }
        // V tile natural: Vs[k][c]
        #pragma unroll
        for (int it = 0; it < 8; it++) {
            int idx = t + it * 256;
            int r = idx >> 4;
            int c = (idx & 15) * 4;
            float4 v = *(const float4*)(kvbase + (size_t)r * (2 * DM) + HD + c);
            *(float4*)&Vs[r * V_STR + c] = v;
        }
        __syncthreads();

        // ---- S = Q @ K^T : 8x8 micro-tile ----
        float s[8][8];
        #pragma unroll
        for (int i = 0; i < 8; i++)
            #pragma unroll
            for (int j = 0; j < 8; j++) s[i][j] = 0.0f;

        #pragma unroll 4
        for (int kk = 0; kk < HD; kk++) {
            float4 a0 = *(const float4*)&Qs[kk * QK_STR + r0 + 0];
            float4 a1 = *(const float4*)&Qs[kk * QK_STR + r0 + 4];
            float4 b0 = *(const float4*)&Ks[kk * QK_STR + c0 + 0];
            float4 b1 = *(const float4*)&Ks[kk * QK_STR + c0 + 4];
            float a[8] = {a0.x, a0.y, a0.z, a0.w, a1.x, a1.y, a1.z, a1.w};
            float bb[8] = {b0.x, b0.y, b0.z, b0.w, b1.x, b1.y, b1.z, b1.w};
            #pragma unroll
            for (int i = 0; i < 8; i++)
                #pragma unroll
                for (int j = 0; j < 8; j++)
                    s[i][j] += a[i] * bb[j];
        }

        // ---- Online softmax in registers ----
        // Row r0+i is owned by the 16 lanes of this half-warp (same ty).
        #pragma unroll
        for (int i = 0; i < 8; i++) {
            float mx = s[i][0];
            #pragma unroll
            for (int j = 1; j < 8; j++) mx = fmaxf(mx, s[i][j]);
            mx = fmaxf(mx, __shfl_xor_sync(0xffffffffu, mx, 1));
            mx = fmaxf(mx, __shfl_xor_sync(0xffffffffu, mx, 2));
            mx = fmaxf(mx, __shfl_xor_sync(0xffffffffu, mx, 4));
            mx = fmaxf(mx, __shfl_xor_sync(0xffffffffu, mx, 8));

            const float m_new = fmaxf(m_r[i], mx);
            const float alpha = __expf(m_r[i] - m_new);
            m_r[i] = m_new;

            float lsum = 0.0f;
            #pragma unroll
            for (int j = 0; j < 8; j++) {
                float p = __expf(s[i][j] - m_new);
                s[i][j] = p;
                lsum += p;
            }
            lsum += __shfl_xor_sync(0xffffffffu, lsum, 1);
            lsum += __shfl_xor_sync(0xffffffffu, lsum, 2);
            lsum += __shfl_xor_sync(0xffffffffu, lsum, 4);
            lsum += __shfl_xor_sync(0xffffffffu, lsum, 8);

            l_r[i] = l_r[i] * alpha + lsum;
            #pragma unroll
            for (int c = 0; c < 4; c++) o[i][c] *= alpha;
        }

        // ---- Store P (conflict-free float4 rows) ----
        #pragma unroll
        for (int i = 0; i < 8; i++) {
            *(float4*)&Ps[(r0 + i) * P_STR + c0 + 0] =
                make_float4(s[i][0], s[i][1], s[i][2], s[i][3]);
            *(float4*)&Ps[(r0 + i) * P_STR + c0 + 4] =
                make_float4(s[i][4], s[i][5], s[i][6], s[i][7]);
        }
        __syncthreads();

        // ---- O += P @ V : 8x4 micro-tile, 4 kk per step ----
        #pragma unroll 2
        for (int kk = 0; kk < BKV2; kk += 4) {
            float4 p[8];
            #pragma unroll
            for (int i = 0; i < 8; i++)
                p[i] = *(const float4*)&Ps[(r0 + i) * P_STR + kk];  // broadcast
            float4 v0 = *(const float4*)&Vs[(kk + 0) * V_STR + c0v];
            float4 v1 = *(const float4*)&Vs[(kk + 1) * V_STR + c0v];
            float4 v2 = *(const float4*)&Vs[(kk + 2) * V_STR + c0v];
            float4 v3 = *(const float4*)&Vs[(kk + 3) * V_STR + c0v];
            #pragma unroll
            for (int i = 0; i < 8; i++) {
                o[i][0] += p[i].x * v0.x + p[i].y * v1.x + p[i].z * v2.x + p[i].w * v3.x;
                o[i][1] += p[i].x * v0.y + p[i].y * v1.y + p[i].z * v2.y + p[i].w * v3.y;
                o[i][2] += p[i].x * v0.z + p[i].y * v1.z + p[i].z * v2.z + p[i].w * v3.z;
                o[i][3] += p[i].x * v0.w + p[i].y * v1.w + p[i].z * v2.w + p[i].w * v3.w;
            }
        }
    }

    // ---- Normalize + write out ----
    #pragma unroll
    for (int i = 0; i < 8; i++) {
        const float inv = 1.0f / l_r[i];
        float* dst = &g_att[(size_t)(b * S_LEN + q0 + r0 + i) * DM + h * HD + c0v];
        #pragma unroll
        for (int c = 0; c < 4; c++)
            dst[c] = o[i][c] * inv;
    }
}

// ---------------------------------------------------------------------------
// Host launcher (graph-capturable: kernel launches only)
// ---------------------------------------------------------------------------
extern "C" void kernel_launch(void* const* d_in, const int* in_sizes, int n_in,
                              void* d_out, int out_size)
{
    const float* x   = (const float*)d_in[0];
    const float* y   = (const float*)d_in[1];
    const float* Wkv = (const float*)d_in[2];
    const float* bkv = (const float*)d_in[3];
    const float* Wq  = (const float*)d_in[4];
    const float* bq  = (const float*)d_in[5];
    const float* Wo  = (const float*)d_in[6];
    const float* bo  = (const float*)d_in[7];
    float* out = (float*)d_out;

    float *kv, *q, *att;
    cudaGetSymbolAddress((void**)&kv,  g_kv);
    cudaGetSymbolAddress((void**)&q,   g_q);
    cudaGetSymbolAddress((void**)&att, g_att);

    cudaFuncSetAttribute(flash_attn2,
                         cudaFuncAttributeMaxDynamicSharedMemorySize,
                         FLASH2_SMEM_BYTES);

    dim3 blk(256);

    // kv = x @ Wkv + bkv    [4096, 2048]
    sgemm_bias<<<dim3(2 * DM / BN, MROWS / BM), blk>>>(x, Wkv, bkv, kv, MROWS, 2 * DM, DM);
    // q  = y @ Wq  + bq     [4096, 1024]
    sgemm_bias<<<dim3(DM / BN, MROWS / BM), blk>>>(y, Wq, bq, q, MROWS, DM, DM);
    // attention -> g_att    [4096, 1024]
    flash_attn2<<<dim3(S_LEN / BQ2, BATCH * NHEAD), blk, FLASH2_SMEM_BYTES>>>();
    // out = att @ Wo + bo   [4096, 1024]
    sgemm_bias<<<dim3(DM / BN, MROWS / BM), blk>>>(att, Wo, bo, out, MROWS, DM, DM);
}

// round 4
// speedup vs baseline: 2.4472x; 2.2359x over previous
#include <cuda_runtime.h>
#include <cstdint>

// Problem constants
#define S_LEN 2048
#define BATCH 2
#define NHEAD 16
#define HD    64
#define DM    1024
#define MROWS (BATCH * S_LEN)   // 4096

// Scratch (device globals: no allocations allowed)
__device__ float g_kv [MROWS * 2 * DM];   // 4096 x 2048  (k,v projections)
__device__ float g_q  [MROWS * DM];       // 4096 x 1024
__device__ float g_att[MROWS * DM];       // 4096 x 1024  (attention output)

// ---------------------------------------------------------------------------
// tf32 helpers
// ---------------------------------------------------------------------------
__device__ __forceinline__ float f2tf(float x) {
    uint32_t r;
    asm("cvt.rna.tf32.f32 %0, %1;" : "=r"(r) : "f"(x));
    return __uint_as_float(r);
}

// D = A(16x8,row) * B(8x8,col) + D, tf32 inputs (b32 regs), fp32 accum
__device__ __forceinline__ void mma_tf32(float c[4],
                                         uint32_t a0, uint32_t a1, uint32_t a2, uint32_t a3,
                                         uint32_t b0, uint32_t b1) {
    asm volatile(
        "mma.sync.aligned.m16n8k8.row.col.f32.tf32.tf32.f32 "
        "{%0,%1,%2,%3}, {%4,%5,%6,%7}, {%8,%9}, {%0,%1,%2,%3};"
        : "+f"(c[0]), "+f"(c[1]), "+f"(c[2]), "+f"(c[3])
        : "r"(a0), "r"(a1), "r"(a2), "r"(a3), "r"(b0), "r"(b1));
}

__device__ __forceinline__ uint32_t lds_u32(const float* p) {
    return __float_as_uint(*p);
}

// ---------------------------------------------------------------------------
// tf32 GEMM with bias: C[M,N] = A[M,K] @ W[K,N] + bias[N]
// CTA tile 128x128, BK=32, 256 threads (8 warps). Warp w owns rows [16w,16w+16)
// across all 128 cols -> 16 m16n8 accumulator tiles.
// Smem: As[m][k] (row-major, tf32), Wt[n][k] (W transposed, tf32), stride 36.
// ---------------------------------------------------------------------------
#define GSTR 36

__global__ __launch_bounds__(256) void gemm_tf32(
    const float* __restrict__ A, const float* __restrict__ W,
    const float* __restrict__ bias, float* __restrict__ C,
    int M, int N, int K)
{
    __shared__ float As[128 * GSTR];
    __shared__ float Wt[128 * GSTR];

    const int t    = threadIdx.x;
    const int w    = t >> 5;
    const int lane = t & 31;
    const int g    = lane >> 2;   // 0..7
    const int tg   = lane & 3;    // 0..3
    const int m0   = blockIdx.y * 128;
    const int n0   = blockIdx.x * 128;

    float acc[16][4];
    #pragma unroll
    for (int nt = 0; nt < 16; nt++)
        #pragma unroll
        for (int c = 0; c < 4; c++) acc[nt][c] = 0.0f;

    // loader indices
    const int a_r8 = t >> 3;      // 0..31
    const int a_c4 = t & 7;       // 0..7
    const int w_kr = t >> 3;      // 0..31
    const int w_c8 = t & 7;       // 0..7

    for (int k0 = 0; k0 < K; k0 += 32) {
        __syncthreads();
        // A tile: 128 rows x 32 cols
        #pragma unroll
        for (int it = 0; it < 4; it++) {
            int r = a_r8 + 32 * it;
            float4 v = *(const float4*)(A + (size_t)(m0 + r) * K + k0 + a_c4 * 4);
            float* dst = &As[r * GSTR + a_c4 * 4];
            dst[0] = f2tf(v.x); dst[1] = f2tf(v.y);
            dst[2] = f2tf(v.z); dst[3] = f2tf(v.w);
        }
        // W tile transposed: Wt[n][k], n=0..127, k=0..31
        #pragma unroll
        for (int it = 0; it < 4; it++) {
            int nc = w_c8 + 8 * it;   // float4 col group 0..31
            float4 v = *(const float4*)(W + (size_t)(k0 + w_kr) * N + n0 + nc * 4);
            Wt[(nc * 4 + 0) * GSTR + w_kr] = f2tf(v.x);
            Wt[(nc * 4 + 1) * GSTR + w_kr] = f2tf(v.y);
            Wt[(nc * 4 + 2) * GSTR + w_kr] = f2tf(v.z);
            Wt[(nc * 4 + 3) * GSTR + w_kr] = f2tf(v.w);
        }
        __syncthreads();

        #pragma unroll
        for (int ks = 0; ks < 4; ks++) {
            const int k = ks * 8;
            const float* abase = &As[(w * 16) * GSTR + k];
            uint32_t a0 = lds_u32(abase + (g    ) * GSTR + tg);
            uint32_t a1 = lds_u32(abase + (g + 8) * GSTR + tg);
            uint32_t a2 = lds_u32(abase + (g    ) * GSTR + tg + 4);
            uint32_t a3 = lds_u32(abase + (g + 8) * GSTR + tg + 4);
            #pragma unroll
            for (int nt = 0; nt < 16; nt++) {
                const float* bbase = &Wt[(nt * 8 + g) * GSTR + k];
                uint32_t b0 = lds_u32(bbase + tg);
                uint32_t b1 = lds_u32(bbase + tg + 4);
                mma_tf32(acc[nt], a0, a1, a2, a3, b0, b1);
            }
        }
    }

    // Epilogue: rows 16w+g, 16w+g+8; cols nt*8 + 2tg, +1
    const int rA = m0 + w * 16 + g;
    const int rB = rA + 8;
    #pragma unroll
    for (int nt = 0; nt < 16; nt++) {
        const int col = n0 + nt * 8 + tg * 2;
        float2 bb = *(const float2*)(bias + col);
        *(float2*)(C + (size_t)rA * N + col) = make_float2(acc[nt][0] + bb.x, acc[nt][1] + bb.y);
        *(float2*)(C + (size_t)rB * N + col) = make_float2(acc[nt][2] + bb.x, acc[nt][3] + bb.y);
    }
}

// ---------------------------------------------------------------------------
// Flash attention, tf32 tensor-core version.
// CTA = one (b,h) x 128-query block; 256 threads (8 warps).
// Warp w owns query rows [16w, 16w+16) -> softmax fully warp-local.
// S phase: 16 col tiles (128 kv cols); PV phase: 8 col tiles (64 dims).
// Smem strides chosen so fragment reads are bank-conflict-free.
// ---------------------------------------------------------------------------
#define QK_STR2 68     // == 4 (mod 32)
#define V_STR2  132    // == 4 (mod 32)
#define P_STR2  132    // == 4 (mod 32)

#define FLASH3_SMEM_FLOATS (128 * QK_STR2 * 2 + 64 * V_STR2 + 128 * P_STR2)
#define FLASH3_SMEM_BYTES  (FLASH3_SMEM_FLOATS * 4)

__global__ __launch_bounds__(256) void flash_tf32()
{
    extern __shared__ float sm[];
    float* Qs = sm;                        // [128][QK_STR2]  Q rows, tf32, pre-scaled
    float* Ks = Qs + 128 * QK_STR2;        // [128][QK_STR2]  K rows (natural = col-major B)
    float* Vt = Ks + 128 * QK_STR2;        // [64][V_STR2]    V transposed: Vt[d][kv]
    float* Ps = Vt + 64 * V_STR2;          // [128][P_STR2]   probabilities, tf32

    const int t    = threadIdx.x;
    const int w    = t >> 5;
    const int lane = t & 31;
    const int g    = lane >> 2;
    const int tg   = lane & 3;
    const int bh   = blockIdx.y;
    const int b    = bh >> 4;
    const int h    = bh & 15;
    const int q0   = blockIdx.x * 128;
    const float scale = 0.125f;

    // ---- Load Q tile: Qs[r][d], scaled + tf32 ----
    {
        const float* qbase = g_q + (size_t)(b * S_LEN + q0) * DM + h * HD;
        #pragma unroll
        for (int it = 0; it < 8; it++) {
            int lin = t + it * 256;
            int r   = lin >> 4;
            int dc  = lin & 15;
            float4 v = *(const float4*)(qbase + (size_t)r * DM + dc * 4);
            float* dst = &Qs[r * QK_STR2 + dc * 4];
            dst[0] = f2tf(v.x * scale); dst[1] = f2tf(v.y * scale);
            dst[2] = f2tf(v.z * scale); dst[3] = f2tf(v.w * scale);
        }
    }

    float mA = -1e30f, mB = -1e30f, lA = 0.0f, lB = 0.0f;
    float o[8][4];
    #pragma unroll
    for (int nt = 0; nt < 8; nt++)
        #pragma unroll
        for (int c = 0; c < 4; c++) o[nt][c] = 0.0f;

    const int rW = w * 16;         // warp's row band
    const float* Arow  = &Ps[(rW + g) * P_STR2];
    const float* Arow8 = &Ps[(rW + g + 8) * P_STR2];

    for (int kb = 0; kb < S_LEN / 128; kb++) {
        __syncthreads();   // all warps done reading Ks/Vt from previous block

        const float* kvbase = g_kv + (size_t)(b * S_LEN + kb * 128) * (2 * DM) + h * 2 * HD;

        // K tile natural: Ks[kv][d]
        #pragma unroll
        for (int it = 0; it < 8; it++) {
            int lin = t + it * 256;
            int r   = lin >> 4;
            int dc  = lin & 15;
            float4 v = *(const float4*)(kvbase + (size_t)r * (2 * DM) + dc * 4);
            float* dst = &Ks[r * QK_STR2 + dc * 4];
            dst[0] = f2tf(v.x); dst[1] = f2tf(v.y);
            dst[2] = f2tf(v.z); dst[3] = f2tf(v.w);
        }
        // V tile transposed: Vt[d][kv]
        #pragma unroll
        for (int it = 0; it < 8; it++) {
            int dc  = (t & 7) + 8 * (it & 1);        // 0..15 (d float4 group)
            int kvr = (t >> 3) + 32 * (it >> 1);     // 0..127
            float4 v = *(const float4*)(kvbase + (size_t)kvr * (2 * DM) + HD + dc * 4);
            Vt[(dc * 4 + 0) * V_STR2 + kvr] = f2tf(v.x);
            Vt[(dc * 4 + 1) * V_STR2 + kvr] = f2tf(v.y);
            Vt[(dc * 4 + 2) * V_STR2 + kvr] = f2tf(v.z);
            Vt[(dc * 4 + 3) * V_STR2 + kvr] = f2tf(v.w);
        }
        __syncthreads();

        // ---- S = Q @ K^T : warp computes 16 rows x 128 cols = 16 tiles ----
        float s[16][4];
        #pragma unroll
        for (int nt = 0; nt < 16; nt++)
            #pragma unroll
            for (int c = 0; c < 4; c++) s[nt][c] = 0.0f;

        #pragma unroll
        for (int ks = 0; ks < 8; ks++) {
            const int k = ks * 8;
            const float* abase = &Qs[rW * QK_STR2 + k];
            uint32_t a0 = lds_u32(abase + (g    ) * QK_STR2 + tg);
            uint32_t a1 = lds_u32(abase + (g + 8) * QK_STR2 + tg);
            uint32_t a2 = lds_u32(abase + (g    ) * QK_STR2 + tg + 4);
            uint32_t a3 = lds_u32(abase + (g + 8) * QK_STR2 + tg + 4);
            #pragma unroll
            for (int nt = 0; nt < 16; nt++) {
                const float* bbase = &Ks[(nt * 8 + g) * QK_STR2 + k];
                uint32_t b0 = lds_u32(bbase + tg);
                uint32_t b1 = lds_u32(bbase + tg + 4);
                mma_tf32(s[nt], a0, a1, a2, a3, b0, b1);
            }
        }

        // ---- Online softmax (warp-local; rows rW+g and rW+g+8) ----
        float mxA = -1e30f, mxB = -1e30f;
        #pragma unroll
        for (int nt = 0; nt < 16; nt++) {
            mxA = fmaxf(mxA, fmaxf(s[nt][0], s[nt][1]));
            mxB = fmaxf(mxB, fmaxf(s[nt][2], s[nt][3]));
        }
        mxA = fmaxf(mxA, __shfl_xor_sync(0xffffffffu, mxA, 1));
        mxA = fmaxf(mxA, __shfl_xor_sync(0xffffffffu, mxA, 2));
        mxB = fmaxf(mxB, __shfl_xor_sync(0xffffffffu, mxB, 1));
        mxB = fmaxf(mxB, __shfl_xor_sync(0xffffffffu, mxB, 2));

        const float mnA = fmaxf(mA, mxA);
        const float mnB = fmaxf(mB, mxB);
        const float aA  = __expf(mA - mnA);
        const float aB  = __expf(mB - mnB);
        mA = mnA; mB = mnB;

        float sumA = 0.0f, sumB = 0.0f;
        #pragma unroll
        for (int nt = 0; nt < 16; nt++) {
            s[nt][0] = __expf(s[nt][0] - mnA);
            s[nt][1] = __expf(s[nt][1] - mnA);
            s[nt][2] = __expf(s[nt][2] - mnB);
            s[nt][3] = __expf(s[nt][3] - mnB);
            sumA += s[nt][0] + s[nt][1];
            sumB += s[nt][2] + s[nt][3];
        }
        sumA += __shfl_xor_sync(0xffffffffu, sumA, 1);
        sumA += __shfl_xor_sync(0xffffffffu, sumA, 2);
        sumB += __shfl_xor_sync(0xffffffffu, sumB, 1);
        sumB += __shfl_xor_sync(0xffffffffu, sumB, 2);
        lA = lA * aA + sumA;
        lB = lB * aB + sumB;

        // rescale O
        #pragma unroll
        for (int nt = 0; nt < 8; nt++) {
            o[nt][0] *= aA; o[nt][1] *= aA;
            o[nt][2] *= aB; o[nt][3] *= aB;
        }

        // ---- Store P (tf32) to warp-private band of Ps ----
        #pragma unroll
        for (int nt = 0; nt < 16; nt++) {
            float* pA = &Ps[(rW + g) * P_STR2 + nt * 8 + tg * 2];
            float* pB = &Ps[(rW + g + 8) * P_STR2 + nt * 8 + tg * 2];
            *(float2*)pA = make_float2(f2tf(s[nt][0]), f2tf(s[nt][1]));
            *(float2*)pB = make_float2(f2tf(s[nt][2]), f2tf(s[nt][3]));
        }
        __syncwarp();

        // ---- O += P @ V : 16 rows x 64 cols = 8 tiles, K=128 ----
        #pragma unroll 4
        for (int ks = 0; ks < 16; ks++) {
            const int k = ks * 8;
            uint32_t a0 = lds_u32(Arow  + k + tg);
            uint32_t a1 = lds_u32(Arow8 + k + tg);
            uint32_t a2 = lds_u32(Arow  + k + tg + 4);
            uint32_t a3 = lds_u32(Arow8 + k + tg + 4);
            #pragma unroll
            for (int nt = 0; nt < 8; nt++) {
                const float* bbase = &Vt[(nt * 8 + g) * V_STR2 + k];
                uint32_t b0 = lds_u32(bbase + tg);
                uint32_t b1 = lds_u32(bbase + tg + 4);
                mma_tf32(o[nt], a0, a1, a2, a3, b0, b1);
            }
        }
    }

    // ---- Normalize + write out ----
    const float invA = 1.0f / lA;
    const float invB = 1.0f / lB;
    float* obaseA = g_att + (size_t)(b * S_LEN + q0 + rW + g) * DM + h * HD;
    float* obaseB = g_att + (size_t)(b * S_LEN + q0 + rW + g + 8) * DM + h * HD;
    #pragma unroll
    for (int nt = 0; nt < 8; nt++) {
        const int col = nt * 8 + tg * 2;
        *(float2*)(obaseA + col) = make_float2(o[nt][0] * invA, o[nt][1] * invA);
        *(float2*)(obaseB + col) = make_float2(o[nt][2] * invB, o[nt][3] * invB);
    }
}

// ---------------------------------------------------------------------------
// Host launcher (graph-capturable: kernel launches only)
// ---------------------------------------------------------------------------
extern "C" void kernel_launch(void* const* d_in, const int* in_sizes, int n_in,
                              void* d_out, int out_size)
{
    const float* x   = (const float*)d_in[0];
    const float* y   = (const float*)d_in[1];
    const float* Wkv = (const float*)d_in[2];
    const float* bkv = (const float*)d_in[3];
    const float* Wq  = (const float*)d_in[4];
    const float* bq  = (const float*)d_in[5];
    const float* Wo  = (const float*)d_in[6];
    const float* bo  = (const float*)d_in[7];
    float* out = (float*)d_out;

    float *kv, *q, *att;
    cudaGetSymbolAddress((void**)&kv,  g_kv);
    cudaGetSymbolAddress((void**)&q,   g_q);
    cudaGetSymbolAddress((void**)&att, g_att);

    cudaFuncSetAttribute(flash_tf32,
                         cudaFuncAttributeMaxDynamicSharedMemorySize,
                         FLASH3_SMEM_BYTES);

    dim3 blk(256);

    // kv = x @ Wkv + bkv    [4096, 2048]
    gemm_tf32<<<dim3(2 * DM / 128, MROWS / 128), blk>>>(x, Wkv, bkv, kv, MROWS, 2 * DM, DM);
    // q  = y @ Wq  + bq     [4096, 1024]
    gemm_tf32<<<dim3(DM / 128, MROWS / 128), blk>>>(y, Wq, bq, q, MROWS, DM, DM);
    // attention -> g_att    [4096, 1024]
    flash_tf32<<<dim3(S_LEN / 128, BATCH * NHEAD), blk, FLASH3_SMEM_BYTES>>>();
    // out = att @ Wo + bo   [4096, 1024]
    gemm_tf32<<<dim3(DM / 128, MROWS / 128), blk>>>(att, Wo, bo, out, MROWS, DM, DM);
}

// round 5
// speedup vs baseline: 2.7545x; 1.1256x over previous
#include <cuda_runtime.h>
#include <cstdint>

// Problem constants
#define S_LEN 2048
#define BATCH 2
#define NHEAD 16
#define HD    64
#define DM    1024
#define MROWS (BATCH * S_LEN)   // 4096

// Scratch (device globals: no allocations allowed)
__device__ float g_kv [MROWS * 2 * DM];   // 4096 x 2048
__device__ float g_q  [MROWS * DM];       // 4096 x 1024
__device__ float g_att[MROWS * DM];       // 4096 x 1024

// ---------------------------------------------------------------------------
// tf32 helpers
// ---------------------------------------------------------------------------
__device__ __forceinline__ float f2tf(float x) {
    uint32_t r;
    asm("cvt.rna.tf32.f32 %0, %1;" : "=r"(r) : "f"(x));
    return __uint_as_float(r);
}

__device__ __forceinline__ void mma_tf32(float c[4],
                                         uint32_t a0, uint32_t a1, uint32_t a2, uint32_t a3,
                                         uint32_t b0, uint32_t b1) {
    asm volatile(
        "mma.sync.aligned.m16n8k8.row.col.f32.tf32.tf32.f32 "
        "{%0,%1,%2,%3}, {%4,%5,%6,%7}, {%8,%9}, {%0,%1,%2,%3};"
        : "+f"(c[0]), "+f"(c[1]), "+f"(c[2]), "+f"(c[3])
        : "r"(a0), "r"(a1), "r"(a2), "r"(a3), "r"(b0), "r"(b1));
}

__device__ __forceinline__ uint32_t lds_u32(const float* p) {
    return __float_as_uint(*p);
}

// ---------------------------------------------------------------------------
// GEMM v2: C[M,N] = A[M,K] @ W[K,N] + bias[N]
// CTA tile 256x128, 256 threads = 8 warps in 4(m) x 2(n); warp tile 64x64
// (4 m16 tiles x 8 n8 tiles = 32 mma per k-slice, 128 accum regs).
// BK=16, double-buffered smem, register-staged global prefetch.
// As: natural [256][20] (stride 20 == 4 mod 32, conflict-free LDS + STS.128)
// Wn: natural [16][136]  (stride 136 == 8 mod 32, conflict-free LDS + STS.128)
// ---------------------------------------------------------------------------
#define GBK   16
#define ASTR  20
#define WSTR  136
#define GEMM_STAGE_FLOATS (256 * ASTR + GBK * WSTR)   // 5120 + 2176 = 7296
#define GEMM_SMEM_BYTES   (2 * GEMM_STAGE_FLOATS * 4) // 58368

__global__ __launch_bounds__(256, 1) void gemm_tf32_v2(
    const float* __restrict__ A, const float* __restrict__ W,
    const float* __restrict__ bias, float* __restrict__ C,
    int M, int N, int K)
{
    extern __shared__ float sm[];

    const int t    = threadIdx.x;
    const int w    = t >> 5;
    const int lane = t & 31;
    const int g    = lane >> 2;
    const int tg   = lane & 3;
    const int wm   = w >> 1;       // 0..3
    const int wn   = w & 1;        // 0..1
    const int m0   = blockIdx.y * 256;
    const int n0   = blockIdx.x * 128;

    float acc[4][8][4];
    #pragma unroll
    for (int mi = 0; mi < 4; mi++)
        #pragma unroll
        for (int nt = 0; nt < 8; nt++)
            #pragma unroll
            for (int c = 0; c < 4; c++) acc[mi][nt][c] = 0.0f;

    // loader indices
    const int ar  = t & 63;        // A row base (0..63), +64*it
    const int ac4 = t >> 6;        // A k-group (0..3)
    float4 Areg[4], Wreg[2];

    // ---- prologue: load stage 0 ----
    #pragma unroll
    for (int it = 0; it < 4; it++)
        Areg[it] = *(const float4*)(A + (size_t)(m0 + ar + 64 * it) * K + ac4 * 4);
    #pragma unroll
    for (int it = 0; it < 2; it++) {
        int idx = t + 256 * it;
        int kr  = idx >> 5;
        int nc  = idx & 31;
        Wreg[it] = *(const float4*)(W + (size_t)kr * N + n0 + nc * 4);
    }
    {
        float* As = sm;
        float* Wn = sm + 256 * ASTR;
        #pragma unroll
        for (int it = 0; it < 4; it++) {
            float4 v = Areg[it];
            float4 o = make_float4(f2tf(v.x), f2tf(v.y), f2tf(v.z), f2tf(v.w));
            *(float4*)&As[(ar + 64 * it) * ASTR + ac4 * 4] = o;
        }
        #pragma unroll
        for (int it = 0; it < 2; it++) {
            int idx = t + 256 * it;
            int kr  = idx >> 5;
            int nc  = idx & 31;
            float4 v = Wreg[it];
            float4 o = make_float4(f2tf(v.x), f2tf(v.y), f2tf(v.z), f2tf(v.w));
            *(float4*)&Wn[kr * WSTR + nc * 4] = o;
        }
    }
    __syncthreads();

    const int nstages = K / GBK;
    for (int s = 0; s < nstages; s++) {
        const int p = s & 1;
        const bool more = (s + 1 < nstages);

        // prefetch next stage into registers
        if (more) {
            const int k0 = (s + 1) * GBK;
            #pragma unroll
            for (int it = 0; it < 4; it++)
                Areg[it] = *(const float4*)(A + (size_t)(m0 + ar + 64 * it) * K + k0 + ac4 * 4);
            #pragma unroll
            for (int it = 0; it < 2; it++) {
                int idx = t + 256 * it;
                int kr  = idx >> 5;
                int nc  = idx & 31;
                Wreg[it] = *(const float4*)(W + (size_t)(k0 + kr) * N + n0 + nc * 4);
            }
        }

        // compute current stage
        const float* As = sm + p * GEMM_STAGE_FLOATS;
        const float* Wn = As + 256 * ASTR;
        #pragma unroll
        for (int ks = 0; ks < 2; ks++) {
            uint32_t af[4][4];
            #pragma unroll
            for (int mi = 0; mi < 4; mi++) {
                const float* ab = As + (wm * 64 + mi * 16 + g) * ASTR + ks * 8 + tg;
                af[mi][0] = lds_u32(ab);
                af[mi][1] = lds_u32(ab + 8 * ASTR);
                af[mi][2] = lds_u32(ab + 4);
                af[mi][3] = lds_u32(ab + 8 * ASTR + 4);
            }
            #pragma unroll
            for (int nt = 0; nt < 8; nt++) {
                const float* bb = Wn + (ks * 8 + tg) * WSTR + wn * 64 + nt * 8 + g;
                uint32_t b0 = lds_u32(bb);
                uint32_t b1 = lds_u32(bb + 4 * WSTR);
                #pragma unroll
                for (int mi = 0; mi < 4; mi++)
                    mma_tf32(acc[mi][nt], af[mi][0], af[mi][1], af[mi][2], af[mi][3], b0, b1);
            }
        }

        // store next stage
        if (more) {
            float* Asn = sm + (p ^ 1) * GEMM_STAGE_FLOATS;
            float* Wnn = Asn + 256 * ASTR;
            #pragma unroll
            for (int it = 0; it < 4; it++) {
                float4 v = Areg[it];
                float4 o = make_float4(f2tf(v.x), f2tf(v.y), f2tf(v.z), f2tf(v.w));
                *(float4*)&Asn[(ar + 64 * it) * ASTR + ac4 * 4] = o;
            }
            #pragma unroll
            for (int it = 0; it < 2; it++) {
                int idx = t + 256 * it;
                int kr  = idx >> 5;
                int nc  = idx & 31;
                float4 v = Wreg[it];
                float4 o = make_float4(f2tf(v.x), f2tf(v.y), f2tf(v.z), f2tf(v.w));
                *(float4*)&Wnn[kr * WSTR + nc * 4] = o;
            }
        }
        __syncthreads();
    }

    // epilogue
    #pragma unroll
    for (int mi = 0; mi < 4; mi++) {
        const int rA = m0 + wm * 64 + mi * 16 + g;
        const int rB = rA + 8;
        #pragma unroll
        for (int nt = 0; nt < 8; nt++) {
            const int col = n0 + wn * 64 + nt * 8 + tg * 2;
            float2 bb = *(const float2*)(bias + col);
            *(float2*)(C + (size_t)rA * N + col) =
                make_float2(acc[mi][nt][0] + bb.x, acc[mi][nt][1] + bb.y);
            *(float2*)(C + (size_t)rB * N + col) =
                make_float2(acc[mi][nt][2] + bb.x, acc[mi][nt][3] + bb.y);
        }
    }
}

// ---------------------------------------------------------------------------
// Flash attention v3 (tf32 tensor cores).
// CTA = 128 threads (4 warps) x 64 query rows; warp owns 16 rows.
// - Q fragments held in registers for the whole kernel (no A-LDS in S phase)
// - P transferred from S accumulators to PV A-fragments via warp shuffles
//   (no Ps smem buffer at all)
// - smem = K tile [128][68] + V tile [128][72] = 70 KB -> 3 CTAs/SM
// ---------------------------------------------------------------------------
#define FQ    64
#define KSTR  68
#define VSTR  72
#define FLASH_SMEM_BYTES ((128 * KSTR + 128 * VSTR) * 4)   // 71680

__global__ __launch_bounds__(128, 3) void flash_v3()
{
    extern __shared__ float sm[];
    float* Ks = sm;                 // [128][KSTR]  K natural [kv][d]
    float* Vs = sm + 128 * KSTR;    // [128][VSTR]  V natural [kv][d]

    const int t    = threadIdx.x;
    const int w    = t >> 5;
    const int lane = t & 31;
    const int g    = lane >> 2;
    const int tg   = lane & 3;
    const int bh   = blockIdx.y;
    const int b    = bh >> 4;
    const int h    = bh & 15;
    const int q0   = blockIdx.x * FQ;
    const int rW   = w * 16;
    const float scale = 0.125f;

    // ---- Stage Q through Ks, pull fragments to registers ----
    {
        const float* qbase = g_q + (size_t)(b * S_LEN + q0) * DM + h * HD;
        #pragma unroll
        for (int it = 0; it < 8; it++) {
            int idx = t + 128 * it;
            int r   = idx >> 4;          // 0..63
            int dc  = idx & 15;
            float4 v = *(const float4*)(qbase + (size_t)r * DM + dc * 4);
            float4 o = make_float4(f2tf(v.x * scale), f2tf(v.y * scale),
                                   f2tf(v.z * scale), f2tf(v.w * scale));
            *(float4*)&Ks[r * KSTR + dc * 4] = o;
        }
    }
    __syncthreads();

    uint32_t qf[8][4];
    #pragma unroll
    for (int ks = 0; ks < 8; ks++) {
        const float* ab = Ks + (rW + g) * KSTR + ks * 8 + tg;
        qf[ks][0] = lds_u32(ab);
        qf[ks][1] = lds_u32(ab + 8 * KSTR);
        qf[ks][2] = lds_u32(ab + 4);
        qf[ks][3] = lds_u32(ab + 8 * KSTR + 4);
    }

    float mA = -1e30f, mB = -1e30f, lA = 0.0f, lB = 0.0f;
    float o[8][4];
    #pragma unroll
    for (int nt = 0; nt < 8; nt++)
        #pragma unroll
        for (int c = 0; c < 4; c++) o[nt][c] = 0.0f;

    const int src1 = (lane & 0x1c) | (tg >> 1);
    const int src2 = src1 + 2;
    const bool odd = (tg & 1);

    for (int kb = 0; kb < S_LEN / 128; kb++) {
        __syncthreads();   // previous reads of Ks/Vs (and Q frag pull) complete

        const float* kv = g_kv + (size_t)(b * S_LEN + kb * 128) * (2 * DM) + h * 2 * HD;

        // K tile: 128 rows x 16 float4
        #pragma unroll
        for (int it = 0; it < 16; it++) {
            int idx = t + 128 * it;
            int r   = idx >> 4;
            int dc  = idx & 15;
            float4 v = *(const float4*)(kv + (size_t)r * (2 * DM) + dc * 4);
            float4 q4 = make_float4(f2tf(v.x), f2tf(v.y), f2tf(v.z), f2tf(v.w));
            *(float4*)&Ks[r * KSTR + dc * 4] = q4;
        }
        // V tile
        #pragma unroll
        for (int it = 0; it < 16; it++) {
            int idx = t + 128 * it;
            int r   = idx >> 4;
            int dc  = idx & 15;
            float4 v = *(const float4*)(kv + (size_t)r * (2 * DM) + HD + dc * 4);
            float4 q4 = make_float4(f2tf(v.x), f2tf(v.y), f2tf(v.z), f2tf(v.w));
            *(float4*)&Vs[r * VSTR + dc * 4] = q4;
        }
        __syncthreads();

        // ---- S = Q @ K^T : 16 rows x 128 cols = 16 tiles ----
        float s[16][4];
        #pragma unroll
        for (int nt = 0; nt < 16; nt++)
            #pragma unroll
            for (int c = 0; c < 4; c++) s[nt][c] = 0.0f;

        #pragma unroll
        for (int ks = 0; ks < 8; ks++) {
            #pragma unroll
            for (int nt = 0; nt < 16; nt++) {
                const float* bb = Ks + (nt * 8 + g) * KSTR + ks * 8 + tg;
                uint32_t b0 = lds_u32(bb);
                uint32_t b1 = lds_u32(bb + 4);
                mma_tf32(s[nt], qf[ks][0], qf[ks][1], qf[ks][2], qf[ks][3], b0, b1);
            }
        }

        // ---- Online softmax (warp-local rows rW+g, rW+g+8) ----
        float mxA = -1e30f, mxB = -1e30f;
        #pragma unroll
        for (int nt = 0; nt < 16; nt++) {
            mxA = fmaxf(mxA, fmaxf(s[nt][0], s[nt][1]));
            mxB = fmaxf(mxB, fmaxf(s[nt][2], s[nt][3]));
        }
        mxA = fmaxf(mxA, __shfl_xor_sync(0xffffffffu, mxA, 1));
        mxA = fmaxf(mxA, __shfl_xor_sync(0xffffffffu, mxA, 2));
        mxB = fmaxf(mxB, __shfl_xor_sync(0xffffffffu, mxB, 1));
        mxB = fmaxf(mxB, __shfl_xor_sync(0xffffffffu, mxB, 2));

        const float mnA = fmaxf(mA, mxA);
        const float mnB = fmaxf(mB, mxB);
        const float aA  = __expf(mA - mnA);
        const float aB  = __expf(mB - mnB);
        mA = mnA; mB = mnB;

        float sumA = 0.0f, sumB = 0.0f;
        #pragma unroll
        for (int nt = 0; nt < 16; nt++) {
            float e0 = __expf(s[nt][0] - mnA);
            float e1 = __expf(s[nt][1] - mnA);
            float e2 = __expf(s[nt][2] - mnB);
            float e3 = __expf(s[nt][3] - mnB);
            sumA += e0 + e1;
            sumB += e2 + e3;
            s[nt][0] = f2tf(e0); s[nt][1] = f2tf(e1);
            s[nt][2] = f2tf(e2); s[nt][3] = f2tf(e3);
        }
        sumA += __shfl_xor_sync(0xffffffffu, sumA, 1);
        sumA += __shfl_xor_sync(0xffffffffu, sumA, 2);
        sumB += __shfl_xor_sync(0xffffffffu, sumB, 1);
        sumB += __shfl_xor_sync(0xffffffffu, sumB, 2);
        lA = lA * aA + sumA;
        lB = lB * aB + sumB;

        #pragma unroll
        for (int nt = 0; nt < 8; nt++) {
            o[nt][0] *= aA; o[nt][1] *= aA;
            o[nt][2] *= aB; o[nt][3] *= aB;
        }

        // ---- O += P @ V : A-fragments via warp shuffles ----
        #pragma unroll
        for (int ksp = 0; ksp < 16; ksp++) {
            float v00 = __shfl_sync(0xffffffffu, s[ksp][0], src1);
            float v01 = __shfl_sync(0xffffffffu, s[ksp][1], src1);
            float v02 = __shfl_sync(0xffffffffu, s[ksp][2], src1);
            float v03 = __shfl_sync(0xffffffffu, s[ksp][3], src1);
            float v10 = __shfl_sync(0xffffffffu, s[ksp][0], src2);
            float v11 = __shfl_sync(0xffffffffu, s[ksp][1], src2);
            float v12 = __shfl_sync(0xffffffffu, s[ksp][2], src2);
            float v13 = __shfl_sync(0xffffffffu, s[ksp][3], src2);
            uint32_t a0 = __float_as_uint(odd ? v01 : v00);
            uint32_t a1 = __float_as_uint(odd ? v03 : v02);
            uint32_t a2 = __float_as_uint(odd ? v11 : v10);
            uint32_t a3 = __float_as_uint(odd ? v13 : v12);
            #pragma unroll
            for (int nt = 0; nt < 8; nt++) {
                const float* vb = Vs + (ksp * 8 + tg) * VSTR + nt * 8 + g;
                uint32_t b0 = lds_u32(vb);
                uint32_t b1 = lds_u32(vb + 4 * VSTR);
                mma_tf32(o[nt], a0, a1, a2, a3, b0, b1);
            }
        }
    }

    // ---- Normalize + write out ----
    const float invA = 1.0f / lA;
    const float invB = 1.0f / lB;
    float* obaseA = g_att + (size_t)(b * S_LEN + q0 + rW + g) * DM + h * HD;
    float* obaseB = g_att + (size_t)(b * S_LEN + q0 + rW + g + 8) * DM + h * HD;
    #pragma unroll
    for (int nt = 0; nt < 8; nt++) {
        const int col = nt * 8 + tg * 2;
        *(float2*)(obaseA + col) = make_float2(o[nt][0] * invA, o[nt][1] * invA);
        *(float2*)(obaseB + col) = make_float2(o[nt][2] * invB, o[nt][3] * invB);
    }
}

// ---------------------------------------------------------------------------
// Host launcher (graph-capturable: kernel launches only)
// ---------------------------------------------------------------------------
extern "C" void kernel_launch(void* const* d_in, const int* in_sizes, int n_in,
                              void* d_out, int out_size)
{
    const float* x   = (const float*)d_in[0];
    const float* y   = (const float*)d_in[1];
    const float* Wkv = (const float*)d_in[2];
    const float* bkv = (const float*)d_in[3];
    const float* Wq  = (const float*)d_in[4];
    const float* bq  = (const float*)d_in[5];
    const float* Wo  = (const float*)d_in[6];
    const float* bo  = (const float*)d_in[7];
    float* out = (float*)d_out;

    float *kv, *q, *att;
    cudaGetSymbolAddress((void**)&kv,  g_kv);
    cudaGetSymbolAddress((void**)&q,   g_q);
    cudaGetSymbolAddress((void**)&att, g_att);

    cudaFuncSetAttribute(gemm_tf32_v2,
                         cudaFuncAttributeMaxDynamicSharedMemorySize,
                         GEMM_SMEM_BYTES);
    cudaFuncSetAttribute(flash_v3,
                         cudaFuncAttributeMaxDynamicSharedMemorySize,
                         FLASH_SMEM_BYTES);

    dim3 blk(256);
    dim3 fblk(128);

    // kv = x @ Wkv + bkv    [4096, 2048]
    gemm_tf32_v2<<<dim3(2 * DM / 128, MROWS / 256), blk, GEMM_SMEM_BYTES>>>(
        x, Wkv, bkv, kv, MROWS, 2 * DM, DM);
    // q  = y @ Wq  + bq     [4096, 1024]
    gemm_tf32_v2<<<dim3(DM / 128, MROWS / 256), blk, GEMM_SMEM_BYTES>>>(
        y, Wq, bq, q, MROWS, DM, DM);
    // attention -> g_att
    flash_v3<<<dim3(S_LEN / FQ, BATCH * NHEAD), fblk, FLASH_SMEM_BYTES>>>();
    // out = att @ Wo + bo   [4096, 1024]
    gemm_tf32_v2<<<dim3(DM / 128, MROWS / 256), blk, GEMM_SMEM_BYTES>>>(
        att, Wo, bo, out, MROWS, DM, DM);
}

// round 6
// speedup vs baseline: 2.9068x; 1.0553x over previous
#include <cuda_runtime.h>
#include <cstdint>

// Problem constants
#define S_LEN 2048
#define BATCH 2
#define NHEAD 16
#define HD    64
#define DM    1024
#define MROWS (BATCH * S_LEN)   // 4096

// Scratch (device globals: no allocations allowed)
__device__ float g_kv [MROWS * 2 * DM];   // k,v projections (tf32-rounded)
__device__ float g_q  [MROWS * DM];       // q projection   (tf32-rounded)
__device__ float g_att[MROWS * DM];       // attention out  (tf32-rounded)
__device__ float g_xt [MROWS * DM];       // tf32(x)
__device__ float g_yt [MROWS * DM];       // tf32(y)
__device__ float g_wkvt[DM * 2 * DM];     // tf32(Wkv)
__device__ float g_wqt [DM * DM];         // tf32(Wq)
__device__ float g_wot [DM * DM];         // tf32(Wo)

// ---------------------------------------------------------------------------
// helpers
// ---------------------------------------------------------------------------
__device__ __forceinline__ float f2tf(float x) {
    uint32_t r;
    asm("cvt.rna.tf32.f32 %0, %1;" : "=r"(r) : "f"(x));
    return __uint_as_float(r);
}

__device__ __forceinline__ void mma_tf32(float c[4],
                                         uint32_t a0, uint32_t a1, uint32_t a2, uint32_t a3,
                                         uint32_t b0, uint32_t b1) {
    asm volatile(
        "mma.sync.aligned.m16n8k8.row.col.f32.tf32.tf32.f32 "
        "{%0,%1,%2,%3}, {%4,%5,%6,%7}, {%8,%9}, {%0,%1,%2,%3};"
        : "+f"(c[0]), "+f"(c[1]), "+f"(c[2]), "+f"(c[3])
        : "r"(a0), "r"(a1), "r"(a2), "r"(a3), "r"(b0), "r"(b1));
}

__device__ __forceinline__ void cp16(uint32_t dst, const float* src) {
    asm volatile("cp.async.cg.shared.global [%0], [%1], 16;" :: "r"(dst), "l"(src));
}
__device__ __forceinline__ void cp_commit() {
    asm volatile("cp.async.commit_group;");
}
template<int N> __device__ __forceinline__ void cp_wait() {
    asm volatile("cp.async.wait_group %0;" :: "n"(N));
}

// ---------------------------------------------------------------------------
// tf32 conversion pass (run once per input tensor)
// ---------------------------------------------------------------------------
__global__ void conv_tf32(const float4* __restrict__ in, float4* __restrict__ out, int n4)
{
    int i = blockIdx.x * blockDim.x + threadIdx.x;
    const int stride = gridDim.x * blockDim.x;
    for (; i < n4; i += stride) {
        float4 v = in[i];
        out[i] = make_float4(f2tf(v.x), f2tf(v.y), f2tf(v.z), f2tf(v.w));
    }
}

// ---------------------------------------------------------------------------
// GEMM v3: C[M,N] = A[M,K] @ W[K,N] + bias[N]   (A, W already tf32-rounded)
// CTA 128x128, BK=32, 3-stage cp.async pipeline, 256 threads (8 warps 4m x 2n),
// warp tile 32x64 (2 m16 x 8 n8 tiles, 64 accum regs).
// As natural [128][36] (36==4 mod 32); Bs natural [32][132] (132==4 mod 32):
// conflict-free cp.async stores and fragment LDS.
// ---------------------------------------------------------------------------
#define TBM 128
#define TBN 128
#define TBK 32
#define A3STR 36
#define B3STR 132
#define STAGE_F (TBM * A3STR + TBK * B3STR)   // 4608 + 4224 = 8832
#define STAGE_BYTES (STAGE_F * 4)             // 35328
#define GEMM3_SMEM (3 * STAGE_BYTES)          // 105984

__global__ __launch_bounds__(256, 2) void gemm_tf32_v3(
    const float* __restrict__ A, const float* __restrict__ W,
    const float* __restrict__ bias, float* __restrict__ C,
    int M, int N, int K, int round_out)
{
    extern __shared__ float sm[];
    const uint32_t sm_u32 = (uint32_t)__cvta_generic_to_shared(sm);

    const int t    = threadIdx.x;
    const int w    = t >> 5;
    const int lane = t & 31;
    const int g    = lane >> 2;
    const int tg   = lane & 3;
    const int wm   = w >> 1;     // 0..3
    const int wn   = w & 1;      // 0..1
    const int m0   = blockIdx.y * TBM;
    const int n0   = blockIdx.x * TBN;

    // loader mapping
    const int a_row = t >> 1;           // 0..127
    const int a_off = (t & 1) * 16;     // 0 / 16
    const int b_row = t >> 3;           // 0..31
    const int b_off = (t & 7) * 16;     // 0..112

    const float* a_src = A + (size_t)(m0 + a_row) * K + a_off;
    const float* b_src = W + (size_t)b_row * N + n0 + b_off;
    const uint32_t a_dst = sm_u32 + (uint32_t)(a_row * A3STR + a_off) * 4u;
    const uint32_t b_dst = sm_u32 + (uint32_t)(TBM * A3STR + b_row * B3STR + b_off) * 4u;

    float acc[2][8][4];
    #pragma unroll
    for (int mi = 0; mi < 2; mi++)
        #pragma unroll
        for (int nt = 0; nt < 8; nt++)
            #pragma unroll
            for (int c = 0; c < 4; c++) acc[mi][nt][c] = 0.0f;

    const int ntiles = K / TBK;

    // prologue: stages 0,1
    #pragma unroll
    for (int s = 0; s < 2; s++) {
        const int k0 = s * TBK;
        #pragma unroll
        for (int i = 0; i < 4; i++)
            cp16(a_dst + (uint32_t)s * STAGE_BYTES + i * 16, a_src + k0 + i * 4);
        #pragma unroll
        for (int i = 0; i < 4; i++)
            cp16(b_dst + (uint32_t)s * STAGE_BYTES + i * 16, b_src + (size_t)k0 * N + i * 4);
        cp_commit();
    }

    for (int kt = 0; kt < ntiles; kt++) {
        cp_wait<1>();
        __syncthreads();

        if (kt + 2 < ntiles) {
            const int s  = (kt + 2) % 3;
            const int k0 = (kt + 2) * TBK;
            #pragma unroll
            for (int i = 0; i < 4; i++)
                cp16(a_dst + (uint32_t)s * STAGE_BYTES + i * 16, a_src + k0 + i * 4);
            #pragma unroll
            for (int i = 0; i < 4; i++)
                cp16(b_dst + (uint32_t)s * STAGE_BYTES + i * 16, b_src + (size_t)k0 * N + i * 4);
        }
        cp_commit();   // unconditional: keep group accounting uniform

        const float* As = sm + (kt % 3) * STAGE_F;
        const float* Bs = As + TBM * A3STR;

        #pragma unroll
        for (int ks = 0; ks < 4; ks++) {
            uint32_t af[2][4];
            #pragma unroll
            for (int mi = 0; mi < 2; mi++) {
                const float* ab = As + (wm * 32 + mi * 16 + g) * A3STR + ks * 8 + tg;
                af[mi][0] = __float_as_uint(ab[0]);
                af[mi][1] = __float_as_uint(ab[8 * A3STR]);
                af[mi][2] = __float_as_uint(ab[4]);
                af[mi][3] = __float_as_uint(ab[8 * A3STR + 4]);
            }
            #pragma unroll
            for (int nt = 0; nt < 8; nt++) {
                const float* bb = Bs + (ks * 8 + tg) * B3STR + wn * 64 + nt * 8 + g;
                uint32_t b0 = __float_as_uint(bb[0]);
                uint32_t b1 = __float_as_uint(bb[4 * B3STR]);
                mma_tf32(acc[0][nt], af[0][0], af[0][1], af[0][2], af[0][3], b0, b1);
                mma_tf32(acc[1][nt], af[1][0], af[1][1], af[1][2], af[1][3], b0, b1);
            }
        }
    }

    // epilogue
    #pragma unroll
    for (int mi = 0; mi < 2; mi++) {
        const int rA = m0 + wm * 32 + mi * 16 + g;
        const int rB = rA + 8;
        #pragma unroll
        for (int nt = 0; nt < 8; nt++) {
            const int col = n0 + wn * 64 + nt * 8 + tg * 2;
            float2 bb = *(const float2*)(bias + col);
            float2 vA = make_float2(acc[mi][nt][0] + bb.x, acc[mi][nt][1] + bb.y);
            float2 vB = make_float2(acc[mi][nt][2] + bb.x, acc[mi][nt][3] + bb.y);
            if (round_out) {
                vA.x = f2tf(vA.x); vA.y = f2tf(vA.y);
                vB.x = f2tf(vB.x); vB.y = f2tf(vB.y);
            }
            *(float2*)(C + (size_t)rA * N + col) = vA;
            *(float2*)(C + (size_t)rB * N + col) = vB;
        }
    }
}

// ---------------------------------------------------------------------------
// Flash attention v4 (tf32 tensor cores, cp.async tile loads).
// CTA = 128 threads (4 warps) x 64 query rows; warp owns 16 rows.
// g_q / g_kv are already tf32-rounded by the GEMM epilogues.
// ---------------------------------------------------------------------------
#define FQ    64
#define KSTR  68
#define VSTR  72
#define FLASH_SMEM_BYTES ((128 * KSTR + 128 * VSTR) * 4)   // 71680

__global__ __launch_bounds__(128, 3) void flash_v4()
{
    extern __shared__ float sm[];
    float* Ks = sm;                 // [128][KSTR]
    float* Vs = sm + 128 * KSTR;    // [128][VSTR]
    const uint32_t ks_u32 = (uint32_t)__cvta_generic_to_shared(Ks);
    const uint32_t vs_u32 = (uint32_t)__cvta_generic_to_shared(Vs);

    const int t    = threadIdx.x;
    const int w    = t >> 5;
    const int lane = t & 31;
    const int g    = lane >> 2;
    const int tg   = lane & 3;
    const int bh   = blockIdx.y;
    const int b    = bh >> 4;
    const int h    = bh & 15;
    const int q0   = blockIdx.x * FQ;
    const int rW   = w * 16;

    // ---- Stage Q (64 rows) into Ks via cp.async, then pull fragments ----
    {
        const float* qbase = g_q + (size_t)(b * S_LEN + q0) * DM + h * HD;
        #pragma unroll
        for (int it = 0; it < 8; it++) {
            int idx = t + 128 * it;
            int r   = idx >> 4;
            int c4  = (idx & 15) * 4;
            cp16(ks_u32 + (uint32_t)(r * KSTR + c4) * 4u, qbase + (size_t)r * DM + c4);
        }
        cp_commit();
        cp_wait<0>();
        __syncthreads();
    }

    uint32_t qf[8][4];
    #pragma unroll
    for (int ks = 0; ks < 8; ks++) {
        const float* ab = Ks + (rW + g) * KSTR + ks * 8 + tg;
        qf[ks][0] = __float_as_uint(ab[0]            * 0.125f);  // exact in tf32
        qf[ks][1] = __float_as_uint(ab[8 * KSTR]     * 0.125f);
        qf[ks][2] = __float_as_uint(ab[4]            * 0.125f);
        qf[ks][3] = __float_as_uint(ab[8 * KSTR + 4] * 0.125f);
    }

    float mA = -1e30f, mB = -1e30f, lA = 0.0f, lB = 0.0f;
    float o[8][4];
    #pragma unroll
    for (int nt = 0; nt < 8; nt++)
        #pragma unroll
        for (int c = 0; c < 4; c++) o[nt][c] = 0.0f;

    const int src1 = (lane & 0x1c) | (tg >> 1);
    const int src2 = src1 + 2;
    const bool odd = (tg & 1);

    for (int kb = 0; kb < S_LEN / 128; kb++) {
        __syncthreads();   // previous Ks/Vs readers done (covers Q pull on kb=0)

        const float* kv = g_kv + (size_t)(b * S_LEN + kb * 128) * (2 * DM) + h * 2 * HD;

        #pragma unroll
        for (int it = 0; it < 16; it++) {
            int idx = t + 128 * it;
            int r   = idx >> 4;
            int c4  = (idx & 15) * 4;
            const float* row = kv + (size_t)r * (2 * DM);
            cp16(ks_u32 + (uint32_t)(r * KSTR + c4) * 4u, row + c4);
            cp16(vs_u32 + (uint32_t)(r * VSTR + c4) * 4u, row + HD + c4);
        }
        cp_commit();
        cp_wait<0>();
        __syncthreads();

        // ---- S = Q @ K^T ----
        float s[16][4];
        #pragma unroll
        for (int nt = 0; nt < 16; nt++)
            #pragma unroll
            for (int c = 0; c < 4; c++) s[nt][c] = 0.0f;

        #pragma unroll
        for (int ks = 0; ks < 8; ks++) {
            #pragma unroll
            for (int nt = 0; nt < 16; nt++) {
                const float* bb = Ks + (nt * 8 + g) * KSTR + ks * 8 + tg;
                uint32_t b0 = __float_as_uint(bb[0]);
                uint32_t b1 = __float_as_uint(bb[4]);
                mma_tf32(s[nt], qf[ks][0], qf[ks][1], qf[ks][2], qf[ks][3], b0, b1);
            }
        }

        // ---- Online softmax ----
        float mxA = -1e30f, mxB = -1e30f;
        #pragma unroll
        for (int nt = 0; nt < 16; nt++) {
            mxA = fmaxf(mxA, fmaxf(s[nt][0], s[nt][1]));
            mxB = fmaxf(mxB, fmaxf(s[nt][2], s[nt][3]));
        }
        mxA = fmaxf(mxA, __shfl_xor_sync(0xffffffffu, mxA, 1));
        mxA = fmaxf(mxA, __shfl_xor_sync(0xffffffffu, mxA, 2));
        mxB = fmaxf(mxB, __shfl_xor_sync(0xffffffffu, mxB, 1));
        mxB = fmaxf(mxB, __shfl_xor_sync(0xffffffffu, mxB, 2));

        const float mnA = fmaxf(mA, mxA);
        const float mnB = fmaxf(mB, mxB);
        const float aA  = __expf(mA - mnA);
        const float aB  = __expf(mB - mnB);
        mA = mnA; mB = mnB;

        float sumA = 0.0f, sumB = 0.0f;
        #pragma unroll
        for (int nt = 0; nt < 16; nt++) {
            float e0 = __expf(s[nt][0] - mnA);
            float e1 = __expf(s[nt][1] - mnA);
            float e2 = __expf(s[nt][2] - mnB);
            float e3 = __expf(s[nt][3] - mnB);
            sumA += e0 + e1;
            sumB += e2 + e3;
            s[nt][0] = f2tf(e0); s[nt][1] = f2tf(e1);
            s[nt][2] = f2tf(e2); s[nt][3] = f2tf(e3);
        }
        sumA += __shfl_xor_sync(0xffffffffu, sumA, 1);
        sumA += __shfl_xor_sync(0xffffffffu, sumA, 2);
        sumB += __shfl_xor_sync(0xffffffffu, sumB, 1);
        sumB += __shfl_xor_sync(0xffffffffu, sumB, 2);
        lA = lA * aA + sumA;
        lB = lB * aB + sumB;

        #pragma unroll
        for (int nt = 0; nt < 8; nt++) {
            o[nt][0] *= aA; o[nt][1] *= aA;
            o[nt][2] *= aB; o[nt][3] *= aB;
        }

        // ---- O += P @ V (A-fragments via warp shuffles) ----
        #pragma unroll
        for (int ksp = 0; ksp < 16; ksp++) {
            float v00 = __shfl_sync(0xffffffffu, s[ksp][0], src1);
            float v01 = __shfl_sync(0xffffffffu, s[ksp][1], src1);
            float v02 = __shfl_sync(0xffffffffu, s[ksp][2], src1);
            float v03 = __shfl_sync(0xffffffffu, s[ksp][3], src1);
            float v10 = __shfl_sync(0xffffffffu, s[ksp][0], src2);
            float v11 = __shfl_sync(0xffffffffu, s[ksp][1], src2);
            float v12 = __shfl_sync(0xffffffffu, s[ksp][2], src2);
            float v13 = __shfl_sync(0xffffffffu, s[ksp][3], src2);
            uint32_t a0 = __float_as_uint(odd ? v01 : v00);
            uint32_t a1 = __float_as_uint(odd ? v03 : v02);
            uint32_t a2 = __float_as_uint(odd ? v11 : v10);
            uint32_t a3 = __float_as_uint(odd ? v13 : v12);
            #pragma unroll
            for (int nt = 0; nt < 8; nt++) {
                const float* vb = Vs + (ksp * 8 + tg) * VSTR + nt * 8 + g;
                uint32_t b0 = __float_as_uint(vb[0]);
                uint32_t b1 = __float_as_uint(vb[4 * VSTR]);
                mma_tf32(o[nt], a0, a1, a2, a3, b0, b1);
            }
        }
    }

    // ---- Normalize + write out (tf32-rounded: consumed by final GEMM) ----
    const float invA = 1.0f / lA;
    const float invB = 1.0f / lB;
    float* obaseA = g_att + (size_t)(b * S_LEN + q0 + rW + g) * DM + h * HD;
    float* obaseB = g_att + (size_t)(b * S_LEN + q0 + rW + g + 8) * DM + h * HD;
    #pragma unroll
    for (int nt = 0; nt < 8; nt++) {
        const int col = nt * 8 + tg * 2;
        *(float2*)(obaseA + col) = make_float2(f2tf(o[nt][0] * invA), f2tf(o[nt][1] * invA));
        *(float2*)(obaseB + col) = make_float2(f2tf(o[nt][2] * invB), f2tf(o[nt][3] * invB));
    }
}

// ---------------------------------------------------------------------------
// Host launcher (graph-capturable: kernel launches only)
// ---------------------------------------------------------------------------
extern "C" void kernel_launch(void* const* d_in, const int* in_sizes, int n_in,
                              void* d_out, int out_size)
{
    const float* x   = (const float*)d_in[0];
    const float* y   = (const float*)d_in[1];
    const float* Wkv = (const float*)d_in[2];
    const float* bkv = (const float*)d_in[3];
    const float* Wq  = (const float*)d_in[4];
    const float* bq  = (const float*)d_in[5];
    const float* Wo  = (const float*)d_in[6];
    const float* bo  = (const float*)d_in[7];
    float* out = (float*)d_out;

    float *kv, *q, *att, *xt, *yt, *wkvt, *wqt, *wot;
    cudaGetSymbolAddress((void**)&kv,   g_kv);
    cudaGetSymbolAddress((void**)&q,    g_q);
    cudaGetSymbolAddress((void**)&att,  g_att);
    cudaGetSymbolAddress((void**)&xt,   g_xt);
    cudaGetSymbolAddress((void**)&yt,   g_yt);
    cudaGetSymbolAddress((void**)&wkvt, g_wkvt);
    cudaGetSymbolAddress((void**)&wqt,  g_wqt);
    cudaGetSymbolAddress((void**)&wot,  g_wot);

    cudaFuncSetAttribute(gemm_tf32_v3,
                         cudaFuncAttributeMaxDynamicSharedMemorySize, GEMM3_SMEM);
    cudaFuncSetAttribute(flash_v4,
                         cudaFuncAttributeMaxDynamicSharedMemorySize, FLASH_SMEM_BYTES);

    dim3 blk(256);
    dim3 fblk(128);
    const int cvb = 1024;

    // tf32 conversion passes
    conv_tf32<<<cvb, 256>>>((const float4*)x,   (float4*)xt,   MROWS * DM / 4);
    conv_tf32<<<cvb, 256>>>((const float4*)y,   (float4*)yt,   MROWS * DM / 4);
    conv_tf32<<<cvb, 256>>>((const float4*)Wkv, (float4*)wkvt, DM * 2 * DM / 4);
    conv_tf32<<<cvb, 256>>>((const float4*)Wq,  (float4*)wqt,  DM * DM / 4);
    conv_tf32<<<cvb, 256>>>((const float4*)Wo,  (float4*)wot,  DM * DM / 4);

    // kv = x @ Wkv + bkv   [4096, 2048]  (tf32-rounded output)
    gemm_tf32_v3<<<dim3(2 * DM / TBN, MROWS / TBM), blk, GEMM3_SMEM>>>(
        xt, wkvt, bkv, kv, MROWS, 2 * DM, DM, 1);
    // q = y @ Wq + bq      [4096, 1024]  (tf32-rounded output)
    gemm_tf32_v3<<<dim3(DM / TBN, MROWS / TBM), blk, GEMM3_SMEM>>>(
        yt, wqt, bq, q, MROWS, DM, DM, 1);
    // attention
    flash_v4<<<dim3(S_LEN / FQ, BATCH * NHEAD), fblk, FLASH_SMEM_BYTES>>>();
    // out = att @ Wo + bo  [4096, 1024]  (full fp32 output)
    gemm_tf32_v3<<<dim3(DM / TBN, MROWS / TBM), blk, GEMM3_SMEM>>>(
        att, wot, bo, out, MROWS, DM, DM, 0);
}

// round 7
// speedup vs baseline: 3.0932x; 1.0641x over previous
#include <cuda_runtime.h>
#include <cstdint>

// Problem constants
#define S_LEN 2048
#define BATCH 2
#define NHEAD 16
#define HD    64
#define DM    1024
#define MROWS (BATCH * S_LEN)   // 4096

// Scratch (device globals: no allocations allowed)
__device__ float g_kv [MROWS * 2 * DM];   // k,v projections (tf32-rounded)
__device__ float g_q  [MROWS * DM];       // q projection   (tf32-rounded)
__device__ float g_att[MROWS * DM];       // attention out  (tf32-rounded)
__device__ float g_xt [MROWS * DM];       // tf32(x)
__device__ float g_yt [MROWS * DM];       // tf32(y)
__device__ float g_wkvt[DM * 2 * DM];     // tf32(Wkv)
__device__ float g_wqt [DM * DM];         // tf32(Wq)
__device__ float g_wot [DM * DM];         // tf32(Wo)

// ---------------------------------------------------------------------------
// helpers
// ---------------------------------------------------------------------------
__device__ __forceinline__ float f2tf(float x) {
    uint32_t r;
    asm("cvt.rna.tf32.f32 %0, %1;" : "=r"(r) : "f"(x));
    return __uint_as_float(r);
}

__device__ __forceinline__ void mma_tf32(float c[4],
                                         uint32_t a0, uint32_t a1, uint32_t a2, uint32_t a3,
                                         uint32_t b0, uint32_t b1) {
    asm volatile(
        "mma.sync.aligned.m16n8k8.row.col.f32.tf32.tf32.f32 "
        "{%0,%1,%2,%3}, {%4,%5,%6,%7}, {%8,%9}, {%0,%1,%2,%3};"
        : "+f"(c[0]), "+f"(c[1]), "+f"(c[2]), "+f"(c[3])
        : "r"(a0), "r"(a1), "r"(a2), "r"(a3), "r"(b0), "r"(b1));
}

__device__ __forceinline__ void cp16(uint32_t dst, const float* src) {
    asm volatile("cp.async.cg.shared.global [%0], [%1], 16;" :: "r"(dst), "l"(src));
}
__device__ __forceinline__ void cp_commit() {
    asm volatile("cp.async.commit_group;");
}
template<int N> __device__ __forceinline__ void cp_wait() {
    asm volatile("cp.async.wait_group %0;" :: "n"(N));
}

// ---------------------------------------------------------------------------
// tf32 conversion pass (run once per input tensor)
// ---------------------------------------------------------------------------
__global__ void conv_tf32(const float4* __restrict__ in, float4* __restrict__ out, int n4)
{
    int i = blockIdx.x * blockDim.x + threadIdx.x;
    const int stride = gridDim.x * blockDim.x;
    for (; i < n4; i += stride) {
        float4 v = in[i];
        out[i] = make_float4(f2tf(v.x), f2tf(v.y), f2tf(v.z), f2tf(v.w));
    }
}

// ---------------------------------------------------------------------------
// GEMM v3 (unchanged from round 6): C = A @ W + bias, cp.async 3-stage.
// ---------------------------------------------------------------------------
#define TBM 128
#define TBN 128
#define TBK 32
#define A3STR 36
#define B3STR 132
#define STAGE_F (TBM * A3STR + TBK * B3STR)
#define STAGE_BYTES (STAGE_F * 4)
#define GEMM3_SMEM (3 * STAGE_BYTES)

__global__ __launch_bounds__(256, 2) void gemm_tf32_v3(
    const float* __restrict__ A, const float* __restrict__ W,
    const float* __restrict__ bias, float* __restrict__ C,
    int M, int N, int K, int round_out)
{
    extern __shared__ float sm[];
    const uint32_t sm_u32 = (uint32_t)__cvta_generic_to_shared(sm);

    const int t    = threadIdx.x;
    const int w    = t >> 5;
    const int lane = t & 31;
    const int g    = lane >> 2;
    const int tg   = lane & 3;
    const int wm   = w >> 1;
    const int wn   = w & 1;
    const int m0   = blockIdx.y * TBM;
    const int n0   = blockIdx.x * TBN;

    const int a_row = t >> 1;
    const int a_off = (t & 1) * 16;
    const int b_row = t >> 3;
    const int b_off = (t & 7) * 16;

    const float* a_src = A + (size_t)(m0 + a_row) * K + a_off;
    const float* b_src = W + (size_t)b_row * N + n0 + b_off;
    const uint32_t a_dst = sm_u32 + (uint32_t)(a_row * A3STR + a_off) * 4u;
    const uint32_t b_dst = sm_u32 + (uint32_t)(TBM * A3STR + b_row * B3STR + b_off) * 4u;

    float acc[2][8][4];
    #pragma unroll
    for (int mi = 0; mi < 2; mi++)
        #pragma unroll
        for (int nt = 0; nt < 8; nt++)
            #pragma unroll
            for (int c = 0; c < 4; c++) acc[mi][nt][c] = 0.0f;

    const int ntiles = K / TBK;

    #pragma unroll
    for (int s = 0; s < 2; s++) {
        const int k0 = s * TBK;
        #pragma unroll
        for (int i = 0; i < 4; i++)
            cp16(a_dst + (uint32_t)s * STAGE_BYTES + i * 16, a_src + k0 + i * 4);
        #pragma unroll
        for (int i = 0; i < 4; i++)
            cp16(b_dst + (uint32_t)s * STAGE_BYTES + i * 16, b_src + (size_t)k0 * N + i * 4);
        cp_commit();
    }

    for (int kt = 0; kt < ntiles; kt++) {
        cp_wait<1>();
        __syncthreads();

        if (kt + 2 < ntiles) {
            const int s  = (kt + 2) % 3;
            const int k0 = (kt + 2) * TBK;
            #pragma unroll
            for (int i = 0; i < 4; i++)
                cp16(a_dst + (uint32_t)s * STAGE_BYTES + i * 16, a_src + k0 + i * 4);
            #pragma unroll
            for (int i = 0; i < 4; i++)
                cp16(b_dst + (uint32_t)s * STAGE_BYTES + i * 16, b_src + (size_t)k0 * N + i * 4);
        }
        cp_commit();

        const float* As = sm + (kt % 3) * STAGE_F;
        const float* Bs = As + TBM * A3STR;

        #pragma unroll
        for (int ks = 0; ks < 4; ks++) {
            uint32_t af[2][4];
            #pragma unroll
            for (int mi = 0; mi < 2; mi++) {
                const float* ab = As + (wm * 32 + mi * 16 + g) * A3STR + ks * 8 + tg;
                af[mi][0] = __float_as_uint(ab[0]);
                af[mi][1] = __float_as_uint(ab[8 * A3STR]);
                af[mi][2] = __float_as_uint(ab[4]);
                af[mi][3] = __float_as_uint(ab[8 * A3STR + 4]);
            }
            #pragma unroll
            for (int nt = 0; nt < 8; nt++) {
                const float* bb = Bs + (ks * 8 + tg) * B3STR + wn * 64 + nt * 8 + g;
                uint32_t b0 = __float_as_uint(bb[0]);
                uint32_t b1 = __float_as_uint(bb[4 * B3STR]);
                mma_tf32(acc[0][nt], af[0][0], af[0][1], af[0][2], af[0][3], b0, b1);
                mma_tf32(acc[1][nt], af[1][0], af[1][1], af[1][2], af[1][3], b0, b1);
            }
        }
    }

    #pragma unroll
    for (int mi = 0; mi < 2; mi++) {
        const int rA = m0 + wm * 32 + mi * 16 + g;
        const int rB = rA + 8;
        #pragma unroll
        for (int nt = 0; nt < 8; nt++) {
            const int col = n0 + wn * 64 + nt * 8 + tg * 2;
            float2 bb = *(const float2*)(bias + col);
            float2 vA = make_float2(acc[mi][nt][0] + bb.x, acc[mi][nt][1] + bb.y);
            float2 vB = make_float2(acc[mi][nt][2] + bb.x, acc[mi][nt][3] + bb.y);
            if (round_out) {
                vA.x = f2tf(vA.x); vA.y = f2tf(vA.y);
                vB.x = f2tf(vB.x); vB.y = f2tf(vB.y);
            }
            *(float2*)(C + (size_t)rA * N + col) = vA;
            *(float2*)(C + (size_t)rB * N + col) = vB;
        }
    }
}

// ---------------------------------------------------------------------------
// Flash attention v5: software-pipelined KV loads.
// CTA = 128 threads (4 warps) x 64 query rows; BKV=64, 2 KV stages,
// one cp.async commit-group per kv-block, prefetch distance 2.
// smem = 2 x (64x68 + 64x72) floats = 71,680 B -> 3 CTAs/SM.
// ---------------------------------------------------------------------------
#define FQ    64
#define FBKV  64
#define KSTR  68
#define VSTR  72
#define KV_STAGE_F (FBKV * KSTR + FBKV * VSTR)     // 8960 floats
#define FLASH5_SMEM (2 * KV_STAGE_F * 4)           // 71680 bytes
#define NKB (S_LEN / FBKV)                         // 32

__global__ __launch_bounds__(128, 3) void flash_v5()
{
    extern __shared__ float sm[];
    const uint32_t sm_u32 = (uint32_t)__cvta_generic_to_shared(sm);

    const int t    = threadIdx.x;
    const int w    = t >> 5;
    const int lane = t & 31;
    const int g    = lane >> 2;
    const int tg   = lane & 3;
    const int bh   = blockIdx.y;
    const int b    = bh >> 4;
    const int h    = bh & 15;
    const int q0   = blockIdx.x * FQ;
    const int rW   = w * 16;

    // loader mapping: 8 iterations x (idx>>4 row, (idx&15)*4 col)
    const int l_r  = t >> 4;          // row base (0..7), +8*it
    const int l_c4 = (t & 15) * 4;    // col 0..60

    // ---- Stage Q (64 rows x 64) into stage-0 K region, pull fragments ----
    {
        const float* qbase = g_q + (size_t)(b * S_LEN + q0) * DM + h * HD;
        #pragma unroll
        for (int it = 0; it < 8; it++) {
            int r = l_r + 8 * it;
            cp16(sm_u32 + (uint32_t)(r * KSTR + l_c4) * 4u, qbase + (size_t)r * DM + l_c4);
        }
        cp_commit();
        cp_wait<0>();
        __syncthreads();
    }

    uint32_t qf[8][4];
    #pragma unroll
    for (int ks = 0; ks < 8; ks++) {
        const float* ab = sm + (rW + g) * KSTR + ks * 8 + tg;
        qf[ks][0] = __float_as_uint(ab[0]            * 0.125f);  // exact in tf32
        qf[ks][1] = __float_as_uint(ab[8 * KSTR]     * 0.125f);
        qf[ks][2] = __float_as_uint(ab[4]            * 0.125f);
        qf[ks][3] = __float_as_uint(ab[8 * KSTR + 4] * 0.125f);
    }
    __syncthreads();   // Q fragment reads done before KV0 overwrites stage 0

    const float* kvbase = g_kv + (size_t)(b * S_LEN) * (2 * DM) + h * 2 * HD;

    // ---- Prologue: issue KV blocks 0 and 1 ----
    #pragma unroll
    for (int s = 0; s < 2; s++) {
        const uint32_t st = sm_u32 + (uint32_t)s * (KV_STAGE_F * 4);
        const float* src = kvbase + (size_t)(s * FBKV) * (2 * DM);
        #pragma unroll
        for (int it = 0; it < 8; it++) {
            int r = l_r + 8 * it;
            const float* row = src + (size_t)r * (2 * DM);
            cp16(st + (uint32_t)(r * KSTR + l_c4) * 4u, row + l_c4);
            cp16(st + (uint32_t)(FBKV * KSTR + r * VSTR + l_c4) * 4u, row + HD + l_c4);
        }
        cp_commit();
    }

    float mA = -1e30f, mB = -1e30f, lA = 0.0f, lB = 0.0f;
    float o[8][4];
    #pragma unroll
    for (int nt = 0; nt < 8; nt++)
        #pragma unroll
        for (int c = 0; c < 4; c++) o[nt][c] = 0.0f;

    const int src1 = (lane & 0x1c) | (tg >> 1);
    const int src2 = src1 + 2;
    const bool odd = (tg & 1);

    for (int kb = 0; kb < NKB; kb++) {
        const int p = kb & 1;
        const float* Kp = sm + p * KV_STAGE_F;
        const float* Vp = Kp + FBKV * KSTR;

        cp_wait<1>();      // KV[kb] landed (only KV[kb+1] may remain pending)
        __syncthreads();

        // ---- S = Q @ K^T : 16 rows x 64 cols = 8 tiles ----
        float s[8][4];
        #pragma unroll
        for (int nt = 0; nt < 8; nt++)
            #pragma unroll
            for (int c = 0; c < 4; c++) s[nt][c] = 0.0f;

        #pragma unroll
        for (int ks = 0; ks < 8; ks++) {
            #pragma unroll
            for (int nt = 0; nt < 8; nt++) {
                const float* bb = Kp + (nt * 8 + g) * KSTR + ks * 8 + tg;
                uint32_t b0 = __float_as_uint(bb[0]);
                uint32_t b1 = __float_as_uint(bb[4]);
                mma_tf32(s[nt], qf[ks][0], qf[ks][1], qf[ks][2], qf[ks][3], b0, b1);
            }
        }

        // ---- Online softmax (warp-local rows rW+g, rW+g+8) ----
        float mxA = -1e30f, mxB = -1e30f;
        #pragma unroll
        for (int nt = 0; nt < 8; nt++) {
            mxA = fmaxf(mxA, fmaxf(s[nt][0], s[nt][1]));
            mxB = fmaxf(mxB, fmaxf(s[nt][2], s[nt][3]));
        }
        mxA = fmaxf(mxA, __shfl_xor_sync(0xffffffffu, mxA, 1));
        mxA = fmaxf(mxA, __shfl_xor_sync(0xffffffffu, mxA, 2));
        mxB = fmaxf(mxB, __shfl_xor_sync(0xffffffffu, mxB, 1));
        mxB = fmaxf(mxB, __shfl_xor_sync(0xffffffffu, mxB, 2));

        const float mnA = fmaxf(mA, mxA);
        const float mnB = fmaxf(mB, mxB);
        const float aA  = __expf(mA - mnA);
        const float aB  = __expf(mB - mnB);
        mA = mnA; mB = mnB;

        float sumA = 0.0f, sumB = 0.0f;
        #pragma unroll
        for (int nt = 0; nt < 8; nt++) {
            float e0 = __expf(s[nt][0] - mnA);
            float e1 = __expf(s[nt][1] - mnA);
            float e2 = __expf(s[nt][2] - mnB);
            float e3 = __expf(s[nt][3] - mnB);
            sumA += e0 + e1;
            sumB += e2 + e3;
            s[nt][0] = f2tf(e0); s[nt][1] = f2tf(e1);
            s[nt][2] = f2tf(e2); s[nt][3] = f2tf(e3);
        }
        sumA += __shfl_xor_sync(0xffffffffu, sumA, 1);
        sumA += __shfl_xor_sync(0xffffffffu, sumA, 2);
        sumB += __shfl_xor_sync(0xffffffffu, sumB, 1);
        sumB += __shfl_xor_sync(0xffffffffu, sumB, 2);
        lA = lA * aA + sumA;
        lB = lB * aB + sumB;

        #pragma unroll
        for (int nt = 0; nt < 8; nt++) {
            o[nt][0] *= aA; o[nt][1] *= aA;
            o[nt][2] *= aB; o[nt][3] *= aB;
        }

        // ---- O += P @ V : A-fragments via warp shuffles ----
        #pragma unroll
        for (int ksp = 0; ksp < 8; ksp++) {
            float v00 = __shfl_sync(0xffffffffu, s[ksp][0], src1);
            float v01 = __shfl_sync(0xffffffffu, s[ksp][1], src1);
            float v02 = __shfl_sync(0xffffffffu, s[ksp][2], src1);
            float v03 = __shfl_sync(0xffffffffu, s[ksp][3], src1);
            float v10 = __shfl_sync(0xffffffffu, s[ksp][0], src2);
            float v11 = __shfl_sync(0xffffffffu, s[ksp][1], src2);
            float v12 = __shfl_sync(0xffffffffu, s[ksp][2], src2);
            float v13 = __shfl_sync(0xffffffffu, s[ksp][3], src2);
            uint32_t a0 = __float_as_uint(odd ? v01 : v00);
            uint32_t a1 = __float_as_uint(odd ? v03 : v02);
            uint32_t a2 = __float_as_uint(odd ? v11 : v10);
            uint32_t a3 = __float_as_uint(odd ? v13 : v12);
            #pragma unroll
            for (int nt = 0; nt < 8; nt++) {
                const float* vb = Vp + (ksp * 8 + tg) * VSTR + nt * 8 + g;
                uint32_t b0 = __float_as_uint(vb[0]);
                uint32_t b1 = __float_as_uint(vb[4 * VSTR]);
                mma_tf32(o[nt], a0, a1, a2, a3, b0, b1);
            }
        }

        __syncthreads();   // all warps done with stage p before overwrite

        // ---- Prefetch KV[kb+2] into stage p ----
        if (kb + 2 < NKB) {
            const uint32_t st = sm_u32 + (uint32_t)p * (KV_STAGE_F * 4);
            const float* src = kvbase + (size_t)((kb + 2) * FBKV) * (2 * DM);
            #pragma unroll
            for (int it = 0; it < 8; it++) {
                int r = l_r + 8 * it;
                const float* row = src + (size_t)r * (2 * DM);
                cp16(st + (uint32_t)(r * KSTR + l_c4) * 4u, row + l_c4);
                cp16(st + (uint32_t)(FBKV * KSTR + r * VSTR + l_c4) * 4u, row + HD + l_c4);
            }
        }
        cp_commit();   // real or empty: keeps group accounting uniform
    }

    // ---- Normalize + write out (tf32-rounded: consumed by final GEMM) ----
    const float invA = 1.0f / lA;
    const float invB = 1.0f / lB;
    float* obaseA = g_att + (size_t)(b * S_LEN + q0 + rW + g) * DM + h * HD;
    float* obaseB = g_att + (size_t)(b * S_LEN + q0 + rW + g + 8) * DM + h * HD;
    #pragma unroll
    for (int nt = 0; nt < 8; nt++) {
        const int col = nt * 8 + tg * 2;
        *(float2*)(obaseA + col) = make_float2(f2tf(o[nt][0] * invA), f2tf(o[nt][1] * invA));
        *(float2*)(obaseB + col) = make_float2(f2tf(o[nt][2] * invB), f2tf(o[nt][3] * invB));
    }
}

// ---------------------------------------------------------------------------
// Host launcher (graph-capturable: kernel launches only)
// ---------------------------------------------------------------------------
extern "C" void kernel_launch(void* const* d_in, const int* in_sizes, int n_in,
                              void* d_out, int out_size)
{
    const float* x   = (const float*)d_in[0];
    const float* y   = (const float*)d_in[1];
    const float* Wkv = (const float*)d_in[2];
    const float* bkv = (const float*)d_in[3];
    const float* Wq  = (const float*)d_in[4];
    const float* bq  = (const float*)d_in[5];
    const float* Wo  = (const float*)d_in[6];
    const float* bo  = (const float*)d_in[7];
    float* out = (float*)d_out;

    float *kv, *q, *att, *xt, *yt, *wkvt, *wqt, *wot;
    cudaGetSymbolAddress((void**)&kv,   g_kv);
    cudaGetSymbolAddress((void**)&q,    g_q);
    cudaGetSymbolAddress((void**)&att,  g_att);
    cudaGetSymbolAddress((void**)&xt,   g_xt);
    cudaGetSymbolAddress((void**)&yt,   g_yt);
    cudaGetSymbolAddress((void**)&wkvt, g_wkvt);
    cudaGetSymbolAddress((void**)&wqt,  g_wqt);
    cudaGetSymbolAddress((void**)&wot,  g_wot);

    cudaFuncSetAttribute(gemm_tf32_v3,
                         cudaFuncAttributeMaxDynamicSharedMemorySize, GEMM3_SMEM);
    cudaFuncSetAttribute(flash_v5,
                         cudaFuncAttributeMaxDynamicSharedMemorySize, FLASH5_SMEM);

    dim3 blk(256);
    dim3 fblk(128);
    const int cvb = 1024;

    conv_tf32<<<cvb, 256>>>((const float4*)x,   (float4*)xt,   MROWS * DM / 4);
    conv_tf32<<<cvb, 256>>>((const float4*)y,   (float4*)yt,   MROWS * DM / 4);
    conv_tf32<<<cvb, 256>>>((const float4*)Wkv, (float4*)wkvt, DM * 2 * DM / 4);
    conv_tf32<<<cvb, 256>>>((const float4*)Wq,  (float4*)wqt,  DM * DM / 4);
    conv_tf32<<<cvb, 256>>>((const float4*)Wo,  (float4*)wot,  DM * DM / 4);

    gemm_tf32_v3<<<dim3(2 * DM / TBN, MROWS / TBM), blk, GEMM3_SMEM>>>(
        xt, wkvt, bkv, kv, MROWS, 2 * DM, DM, 1);
    gemm_tf32_v3<<<dim3(DM / TBN, MROWS / TBM), blk, GEMM3_SMEM>>>(
        yt, wqt, bq, q, MROWS, DM, DM, 1);
    flash_v5<<<dim3(S_LEN / FQ, BATCH * NHEAD), fblk, FLASH5_SMEM>>>();
    gemm_tf32_v3<<<dim3(DM / TBN, MROWS / TBM), blk, GEMM3_SMEM>>>(
        att, wot, bo, out, MROWS, DM, DM, 0);
}